// round 7
// baseline (speedup 1.0000x reference)
#include <cuda_runtime.h>
#include <math.h>

// Problem constants
#define B_   256
#define M_   196
#define E_   1024
#define H_   8
#define DH   128
#define MID_ 64
#define NKV  (B_*M_)            // 50176 rows for key/value2 projections
#define CELU_ALPHA 1.3f
#define EPS_ 1e-5f

// ---------------- scratch (device globals; no allocation allowed) -------------
__device__ float g_q [B_*E_];
__device__ float g_v1[B_*E_];
__device__ float g_k [NKV*E_];
__device__ float g_v2[NKV*E_];

// ---------------- helpers ----------------------------------------------------
static __device__ __forceinline__ float tf32r(float x) {
    unsigned u;
    asm("cvt.rna.tf32.f32 %0, %1;" : "=r"(u) : "f"(x));
    return __uint_as_float(u);
}

// =============================================================================
// Fused projection: Y = GroupNorm(celu(X @ W + b)) * gw + gb
// X: [nrows,1024] row-major, W: [1024,1024] row-major, Y: [nrows,1024]
// Block tile 128x128, BK=16, tf32 mma.sync m16n8k8, double-buffered smem.
// Grid: (8, nrows/128). GroupNorm group (128 ch) == the block's 128-col tile.
// =============================================================================
__global__ void __launch_bounds__(256, 2)
proj_kernel(const float* __restrict__ X, const float* __restrict__ W,
            const float* __restrict__ bias, const float* __restrict__ gw,
            const float* __restrict__ gb, float* __restrict__ Y)
{
    __shared__ __align__(16) float As[2][16][136];   // [buf][k][row]
    __shared__ __align__(16) float Bs[2][16][136];   // [buf][k][col]
    __shared__ float redS[2][128];
    __shared__ float redQ[2][128];

    const int tid  = threadIdx.x;
    const int lane = tid & 31;
    const int warp = tid >> 5;
    const int gid  = lane >> 2;      // 0..7
    const int tig  = lane & 3;       // 0..3
    const int wr   = warp & 3;       // row-warp 0..3
    const int wc   = warp >> 2;      // col-warp 0..1
    const int rowBase = wr * 32;
    const int colBase = wc * 64;
    const int R0 = blockIdx.y * 128;
    const int C0 = blockIdx.x * 128;

    // global->smem load mapping
    const int ar   = tid >> 1;             // A row 0..127
    const int afh  = (tid & 1) * 8;        // A col base within 16-chunk
    const int bk   = tid >> 4;             // B k-row 0..15
    const int bcol = (tid & 15) * 4;       // B col 0..60

    const float* Abase = X + (size_t)(R0 + ar) * 1024 + afh;
    const float* Bbase = W + (size_t)bk * 1024 + C0 + bcol;

    float acc[2][8][4];
#pragma unroll
    for (int mt = 0; mt < 2; mt++)
#pragma unroll
        for (int nt = 0; nt < 8; nt++)
#pragma unroll
            for (int c = 0; c < 4; c++) acc[mt][nt][c] = 0.f;

    float4 pa0, pa1, pb0, pb1;
    // prefetch chunk 0
    pa0 = *(const float4*)(Abase);
    pa1 = *(const float4*)(Abase + 4);
    pb0 = *(const float4*)(Bbase);
    pb1 = *(const float4*)(Bbase + 64);

    // store chunk 0 -> buffer 0 (convert to tf32 once, here)
    {
        As[0][afh+0][ar] = tf32r(pa0.x); As[0][afh+1][ar] = tf32r(pa0.y);
        As[0][afh+2][ar] = tf32r(pa0.z); As[0][afh+3][ar] = tf32r(pa0.w);
        As[0][afh+4][ar] = tf32r(pa1.x); As[0][afh+5][ar] = tf32r(pa1.y);
        As[0][afh+6][ar] = tf32r(pa1.z); As[0][afh+7][ar] = tf32r(pa1.w);
        float4 t0 = make_float4(tf32r(pb0.x), tf32r(pb0.y), tf32r(pb0.z), tf32r(pb0.w));
        float4 t1 = make_float4(tf32r(pb1.x), tf32r(pb1.y), tf32r(pb1.z), tf32r(pb1.w));
        *(float4*)&Bs[0][bk][bcol]      = t0;
        *(float4*)&Bs[0][bk][bcol + 64] = t1;
    }
    __syncthreads();

    for (int ch = 0; ch < 64; ch++) {
        const int cur = ch & 1;
        if (ch < 63) {
            const int k0 = (ch + 1) * 16;
            pa0 = *(const float4*)(Abase + k0);
            pa1 = *(const float4*)(Abase + k0 + 4);
            pb0 = *(const float4*)(Bbase + (size_t)k0 * 1024);
            pb1 = *(const float4*)(Bbase + (size_t)k0 * 1024 + 64);
        }
        // compute on buffer `cur`
#pragma unroll
        for (int kk = 0; kk < 16; kk += 8) {
            unsigned afrag[2][4], bfrag[8][2];
#pragma unroll
            for (int mt = 0; mt < 2; mt++) {
                const int rb = rowBase + mt * 16;
                afrag[mt][0] = __float_as_uint(As[cur][kk+tig  ][rb+gid  ]);
                afrag[mt][1] = __float_as_uint(As[cur][kk+tig  ][rb+gid+8]);
                afrag[mt][2] = __float_as_uint(As[cur][kk+tig+4][rb+gid  ]);
                afrag[mt][3] = __float_as_uint(As[cur][kk+tig+4][rb+gid+8]);
            }
#pragma unroll
            for (int nt = 0; nt < 8; nt++) {
                const int cb = colBase + nt * 8;
                bfrag[nt][0] = __float_as_uint(Bs[cur][kk+tig  ][cb+gid]);
                bfrag[nt][1] = __float_as_uint(Bs[cur][kk+tig+4][cb+gid]);
            }
#pragma unroll
            for (int mt = 0; mt < 2; mt++)
#pragma unroll
                for (int nt = 0; nt < 8; nt++)
                    asm volatile(
                        "mma.sync.aligned.m16n8k8.row.col.f32.tf32.tf32.f32 "
                        "{%0,%1,%2,%3}, {%4,%5,%6,%7}, {%8,%9}, {%0,%1,%2,%3};\n"
                        : "+f"(acc[mt][nt][0]), "+f"(acc[mt][nt][1]),
                          "+f"(acc[mt][nt][2]), "+f"(acc[mt][nt][3])
                        : "r"(afrag[mt][0]), "r"(afrag[mt][1]),
                          "r"(afrag[mt][2]), "r"(afrag[mt][3]),
                          "r"(bfrag[nt][0]), "r"(bfrag[nt][1]));
        }
        if (ch < 63) {
            const int nxt = cur ^ 1;
            As[nxt][afh+0][ar] = tf32r(pa0.x); As[nxt][afh+1][ar] = tf32r(pa0.y);
            As[nxt][afh+2][ar] = tf32r(pa0.z); As[nxt][afh+3][ar] = tf32r(pa0.w);
            As[nxt][afh+4][ar] = tf32r(pa1.x); As[nxt][afh+5][ar] = tf32r(pa1.y);
            As[nxt][afh+6][ar] = tf32r(pa1.z); As[nxt][afh+7][ar] = tf32r(pa1.w);
            float4 t0 = make_float4(tf32r(pb0.x), tf32r(pb0.y), tf32r(pb0.z), tf32r(pb0.w));
            float4 t1 = make_float4(tf32r(pb1.x), tf32r(pb1.y), tf32r(pb1.z), tf32r(pb1.w));
            *(float4*)&Bs[nxt][bk][bcol]      = t0;
            *(float4*)&Bs[nxt][bk][bcol + 64] = t1;
        }
        __syncthreads();
    }

    // ---------------- epilogue: bias + celu + GroupNorm ----------------
    float bvals[16], gwv[16], gbv[16];
#pragma unroll
    for (int nt = 0; nt < 8; nt++)
#pragma unroll
        for (int cc = 0; cc < 2; cc++) {
            const int cg = C0 + colBase + nt * 8 + tig * 2 + cc;
            bvals[nt*2+cc] = bias[cg];
            gwv  [nt*2+cc] = gw[cg];
            gbv  [nt*2+cc] = gb[cg];
        }

#pragma unroll
    for (int mt = 0; mt < 2; mt++)
#pragma unroll
        for (int nt = 0; nt < 8; nt++)
#pragma unroll
            for (int c = 0; c < 4; c++) {
                float x = acc[mt][nt][c] + bvals[nt*2 + (c & 1)];
                acc[mt][nt][c] = (x > 0.f) ? x : CELU_ALPHA * expm1f(x * (1.f / CELU_ALPHA));
            }

    // per-row sum / sumsq over this warp's 64 cols, combine across col-warps
#pragma unroll
    for (int mt = 0; mt < 2; mt++) {
        float s0 = 0.f, q0 = 0.f, s1 = 0.f, q1 = 0.f;
#pragma unroll
        for (int nt = 0; nt < 8; nt++) {
            float v;
            v = acc[mt][nt][0]; s0 += v; q0 += v * v;
            v = acc[mt][nt][1]; s0 += v; q0 += v * v;
            v = acc[mt][nt][2]; s1 += v; q1 += v * v;
            v = acc[mt][nt][3]; s1 += v; q1 += v * v;
        }
        s0 += __shfl_xor_sync(0xffffffffu, s0, 1); s0 += __shfl_xor_sync(0xffffffffu, s0, 2);
        q0 += __shfl_xor_sync(0xffffffffu, q0, 1); q0 += __shfl_xor_sync(0xffffffffu, q0, 2);
        s1 += __shfl_xor_sync(0xffffffffu, s1, 1); s1 += __shfl_xor_sync(0xffffffffu, s1, 2);
        q1 += __shfl_xor_sync(0xffffffffu, q1, 1); q1 += __shfl_xor_sync(0xffffffffu, q1, 2);
        if (tig == 0) {
            const int r0 = rowBase + mt * 16 + gid;
            redS[wc][r0]     = s0; redQ[wc][r0]     = q0;
            redS[wc][r0 + 8] = s1; redQ[wc][r0 + 8] = q1;
        }
    }
    __syncthreads();

#pragma unroll
    for (int mt = 0; mt < 2; mt++)
#pragma unroll
        for (int hf = 0; hf < 2; hf++) {
            const int r = rowBase + mt * 16 + gid + hf * 8;
            const float mu  = (redS[0][r] + redS[1][r]) * (1.f / 128.f);
            const float var = (redQ[0][r] + redQ[1][r]) * (1.f / 128.f) - mu * mu;
            const float inv = rsqrtf(var + EPS_);
            float* yr = Y + (size_t)(R0 + r) * 1024 + C0 + colBase + tig * 2;
#pragma unroll
            for (int nt = 0; nt < 8; nt++) {
                float2 o;
                o.x = (acc[mt][nt][hf*2+0] - mu) * inv * gwv[nt*2+0] + gbv[nt*2+0];
                o.y = (acc[mt][nt][hf*2+1] - mu) * inv * gwv[nt*2+1] + gbv[nt*2+1];
                *(float2*)(yr + nt * 8) = o;
            }
        }
}

// =============================================================================
// Attention stage: one block per (b, h). 256 threads (8 warps).
//   hidden[m,j] = relu( sum_d k[b,m,h,d]*q[b,h,d]*Wb[d,j] + bb[j] )
//   pool[j]     = sum_m hidden*maskf / sum_m maskf
//   score[m]    = hidden[m,:]@Ws + bs  -> masked -1e9 -> softmax -> wts[m]
//   v2p[d]      = sum_m wts[m] * v2[b,m,h,d]
//   out         = v1 * v2p * sigmoid(pool@Wc + bc)
// =============================================================================
__global__ void __launch_bounds__(256)
attn_kernel(const float* __restrict__ q,  const float* __restrict__ v1,
            const float* __restrict__ k,  const float* __restrict__ v2,
            const int*   __restrict__ mask,
            const float* __restrict__ Wb, const float* __restrict__ bb,
            const float* __restrict__ Ws, const float* __restrict__ bs,
            const float* __restrict__ Wc, const float* __restrict__ bc,
            float* __restrict__ out)
{
    __shared__ __align__(16) float WbqT[MID_][132];   // [j][d] = q[d]*Wb[d][j]
    __shared__ __align__(16) float kbuf[8][DH];
    __shared__ float score[M_];
    __shared__ float wts[M_];
    __shared__ float maskf_s[M_];
    __shared__ float poolPart[8][MID_];
    __shared__ float pool[MID_];
    __shared__ float bbS[MID_], WsS[MID_];
    __shared__ float redA[8], redB[8], redC[8];
    __shared__ float v2part[2][DH];
    __shared__ float sMsInv, sMax, sSInv;

    const int tid  = threadIdx.x;
    const int lane = tid & 31;
    const int w    = tid >> 5;
    const int b    = blockIdx.x >> 3;
    const int h    = blockIdx.x & 7;

    const float* qp = q + (size_t)b * E_ + h * DH;

    // build WbqT, load small vectors, zero pool partials
    for (int i = tid; i < DH * MID_; i += 256) {
        const int d = i >> 6, j = i & 63;          // Wb row-major [128][64]
        WbqT[j][d] = qp[d] * Wb[i];
    }
    if (tid < MID_) { bbS[tid] = bb[tid]; WsS[tid] = Ws[tid]; }
    for (int i = tid; i < M_; i += 256) maskf_s[i] = (float)mask[(size_t)b * M_ + i];
    for (int i = tid; i < 8 * MID_; i += 256) ((float*)poolPart)[i] = 0.f;
    __syncthreads();

    // ---- pass 1: hidden GEMM, score, masked pool accumulation ----
    const int j0 = lane, j1 = lane + 32;
    const float* kbase = k + (size_t)b * M_ * E_ + h * DH;
    for (int m = w; m < M_; m += 8) {
        ((float4*)kbuf[w])[lane] = ((const float4*)(kbase + (size_t)m * E_))[lane];
        __syncwarp();
        float a0 = bbS[j0], a1 = bbS[j1];
#pragma unroll
        for (int d = 0; d < DH; d += 4) {
            const float4 av = *(const float4*)&kbuf[w][d];
            const float4 w0 = *(const float4*)&WbqT[j0][d];
            const float4 w1 = *(const float4*)&WbqT[j1][d];
            a0 += av.x * w0.x + av.y * w0.y + av.z * w0.z + av.w * w0.w;
            a1 += av.x * w1.x + av.y * w1.y + av.z * w1.z + av.w * w1.w;
        }
        const float h0 = fmaxf(a0, 0.f), h1 = fmaxf(a1, 0.f);
        const float mf = maskf_s[m];
        poolPart[w][j0] += h0 * mf;
        poolPart[w][j1] += h1 * mf;
        float p = h0 * WsS[j0] + h1 * WsS[j1];
#pragma unroll
        for (int o = 16; o > 0; o >>= 1) p += __shfl_xor_sync(0xffffffffu, p, o);
        if (lane == 0) score[m] = p;
        __syncwarp();
    }
    __syncthreads();

    // ---- pool reduce across warps ----
    if (tid < MID_) {
        float s = 0.f;
#pragma unroll
        for (int ww = 0; ww < 8; ww++) s += poolPart[ww][tid];
        pool[tid] = s;
    }

    // ---- mask sum ----
    {
        float ms = 0.f;
        for (int i = tid; i < M_; i += 256) ms += maskf_s[i];
#pragma unroll
        for (int o = 16; o > 0; o >>= 1) ms += __shfl_xor_sync(0xffffffffu, ms, o);
        if (lane == 0) redA[w] = ms;
    }
    __syncthreads();
    if (tid == 0) {
        float t = 0.f;
#pragma unroll
        for (int ww = 0; ww < 8; ww++) t += redA[ww];
        sMsInv = 1.f / t;
    }

    // ---- masked scores + max ----
    const float bs0 = bs[0];
    {
        float mx = -1e30f;
        for (int i = tid; i < M_; i += 256) {
            float s = (maskf_s[i] != 0.f) ? (score[i] + bs0) : -1e9f;
            score[i] = s;
            mx = fmaxf(mx, s);
        }
#pragma unroll
        for (int o = 16; o > 0; o >>= 1) mx = fmaxf(mx, __shfl_xor_sync(0xffffffffu, mx, o));
        if (lane == 0) redB[w] = mx;
    }
    __syncthreads();
    if (tid == 0) {
        float mx = -1e30f;
#pragma unroll
        for (int ww = 0; ww < 8; ww++) mx = fmaxf(mx, redB[ww]);
        sMax = mx;
    }
    __syncthreads();

    // ---- exp + sum ----
    {
        const float mx = sMax;
        float se = 0.f;
        for (int i = tid; i < M_; i += 256) {
            float e = expf(score[i] - mx);
            wts[i] = e;
            se += e;
        }
#pragma unroll
        for (int o = 16; o > 0; o >>= 1) se += __shfl_xor_sync(0xffffffffu, se, o);
        if (lane == 0) redC[w] = se;
    }
    __syncthreads();
    if (tid == 0) {
        float t = 0.f;
#pragma unroll
        for (int ww = 0; ww < 8; ww++) t += redC[ww];
        sSInv = 1.f / t;
    }
    __syncthreads();

    // ---- v2 weighted pooling: 2 halves x 128 dims ----
    {
        const int half = tid >> 7;         // 0/1
        const int d    = tid & 127;
        const float* v2base = v2 + (size_t)b * M_ * E_ + h * DH + d;
        float accv = 0.f;
        for (int m = half; m < M_; m += 2)
            accv += wts[m] * v2base[(size_t)m * E_];
        v2part[half][d] = accv;
    }
    __syncthreads();

    // ---- channel gate + output ----
    if (tid < DH) {
        const int d = tid;
        const float v2p = (v2part[0][d] + v2part[1][d]) * sSInv;
        const float msInv = sMsInv;
        float ac = bc[d];
#pragma unroll
        for (int j = 0; j < MID_; j++)
            ac += (pool[j] * msInv) * Wc[j * DH + d];
        const float sig = 1.f / (1.f + expf(-ac));
        out[(size_t)b * E_ + h * DH + d] = v1[(size_t)b * E_ + h * DH + d] * v2p * sig;
    }
}

// =============================================================================
// launch
// =============================================================================
extern "C" void kernel_launch(void* const* d_in, const int* in_sizes, int n_in,
                              void* d_out, int out_size)
{
    (void)in_sizes; (void)n_in; (void)out_size;
    const float* query  = (const float*)d_in[0];
    const float* key    = (const float*)d_in[1];
    const int*   mask   = (const int*  )d_in[2];
    const float* value1 = (const float*)d_in[3];
    const float* value2 = (const float*)d_in[4];
    const float* Wq = (const float*)d_in[5];
    const float* bq = (const float*)d_in[6];
    const float* gqw = (const float*)d_in[7];
    const float* gqb = (const float*)d_in[8];
    const float* Wk = (const float*)d_in[9];
    const float* bk = (const float*)d_in[10];
    const float* gkw = (const float*)d_in[11];
    const float* gkb = (const float*)d_in[12];
    const float* Wv1 = (const float*)d_in[13];
    const float* bv1 = (const float*)d_in[14];
    const float* gv1w = (const float*)d_in[15];
    const float* gv1b = (const float*)d_in[16];
    const float* Wv2 = (const float*)d_in[17];
    const float* bv2 = (const float*)d_in[18];
    const float* gv2w = (const float*)d_in[19];
    const float* gv2b = (const float*)d_in[20];
    const float* Wb = (const float*)d_in[21];
    const float* bb = (const float*)d_in[22];
    const float* Ws = (const float*)d_in[23];
    const float* bs = (const float*)d_in[24];
    const float* Wc = (const float*)d_in[25];
    const float* bc = (const float*)d_in[26];
    float* out = (float*)d_out;

    float *dq, *dv1, *dk, *dv2;
    cudaGetSymbolAddress((void**)&dq,  g_q);
    cudaGetSymbolAddress((void**)&dv1, g_v1);
    cudaGetSymbolAddress((void**)&dk,  g_k);
    cudaGetSymbolAddress((void**)&dv2, g_v2);

    dim3 blk(256);
    // small projections (256 rows)
    proj_kernel<<<dim3(8, B_/128),   blk>>>(query,  Wq,  bq,  gqw,  gqb,  dq);
    proj_kernel<<<dim3(8, B_/128),   blk>>>(value1, Wv1, bv1, gv1w, gv1b, dv1);
    // big projections (50176 rows)
    proj_kernel<<<dim3(8, NKV/128),  blk>>>(key,    Wk,  bk,  gkw,  gkb,  dk);
    proj_kernel<<<dim3(8, NKV/128),  blk>>>(value2, Wv2, bv2, gv2w, gv2b, dv2);
    // attention stage
    attn_kernel<<<dim3(B_*H_), blk>>>(dq, dv1, dk, dv2, mask,
                                      Wb, bb, Ws, bs, Wc, bc, out);
}

// round 9
// speedup vs baseline: 1.1325x; 1.1325x over previous
#include <cuda_runtime.h>
#include <math.h>
#include <stdint.h>

// Problem constants
#define B_   256
#define M_   196
#define E_   1024
#define H_   8
#define DH   128
#define MID_ 64
#define NKV  (B_*M_)
#define CELU_ALPHA 1.3f
#define EPS_ 1e-5f

// ---------------- scratch (device globals; no allocation allowed) -------------
__device__ float g_q  [B_*E_];
__device__ float g_v1 [B_*E_];
__device__ float g_k  [NKV*E_];
__device__ float g_v2 [NKV*E_];
__device__ float g_Wkr [E_*E_];
__device__ float g_Wv2r[E_*E_];

// ---------------- helpers ----------------------------------------------------
static __device__ __forceinline__ float tf32r(float x) {
    unsigned u;
    asm("cvt.rna.tf32.f32 %0, %1;" : "=r"(u) : "f"(x));
    return __uint_as_float(u);
}
static __device__ __forceinline__ uint32_t smem_u32(const void* p) {
    uint32_t a;
    asm("{ .reg .u64 t; cvta.to.shared.u64 t, %1; cvt.u32.u64 %0, t; }" : "=r"(a) : "l"(p));
    return a;
}
#define CP_ASYNC16(dst, src) \
    asm volatile("cp.async.cg.shared.global [%0], [%1], 16;" :: "r"(dst), "l"(src))
#define CP_COMMIT() asm volatile("cp.async.commit_group;" ::: "memory")

#define MMA_TF32(acc, af, bf)                                                   \
    asm volatile(                                                               \
        "mma.sync.aligned.m16n8k8.row.col.f32.tf32.tf32.f32 "                   \
        "{%0,%1,%2,%3}, {%4,%5,%6,%7}, {%8,%9}, {%0,%1,%2,%3};\n"               \
        : "+f"((acc)[0]), "+f"((acc)[1]), "+f"((acc)[2]), "+f"((acc)[3])        \
        : "r"((af)[0]), "r"((af)[1]), "r"((af)[2]), "r"((af)[3]),               \
          "r"((bf)[0]), "r"((bf)[1]))

// =============================================================================
// Elementwise tf32-rna round of a weight matrix (1024x1024)
// =============================================================================
__global__ void __launch_bounds__(256)
round_w(const float* __restrict__ W, float* __restrict__ Wr)
{
    const int i = blockIdx.x * 256 + threadIdx.x;   // float4 index
    float4 v = ((const float4*)W)[i];
    ((float4*)Wr)[i] = make_float4(tf32r(v.x), tf32r(v.y), tf32r(v.z), tf32r(v.w));
}

// =============================================================================
// BIG fused projection: Y = GroupNorm(celu(X @ W + b)) * gw + gb
// Block tile 128x256, 8 warps (2 row x 4 col), warp tile 64x64 (mma m16n8k8).
// cp.async double-buffered. A raw fp32 (hw tf32 truncation), W pre-rounded rna.
// Grid: (4, nrows/128). GN groups (128 ch) = col halves of the 256-col tile.
// =============================================================================
#define A_STRIDE 20
#define B_STRIDE 264
#define A_STAGE  (128*A_STRIDE)   // floats per stage (2560)
#define B_STAGE  (16*B_STRIDE)    // floats per stage (4224)
#define OFF_BIAS 0
#define OFF_GW   256
#define OFF_GB   512
#define OFF_REDS 768              // 4*128
#define OFF_REDQ 1280             // 4*128
#define OFF_A    1792             // byte offset 7168 (16-aligned)
#define OFF_B    (OFF_A + 2*A_STAGE)
#define PB_DYN   ((OFF_B + 2*B_STAGE)*4)   // 61440 bytes

__global__ void __launch_bounds__(256)
proj_big(const float* __restrict__ X, const float* __restrict__ Wr,
         const float* __restrict__ bias, const float* __restrict__ gw,
         const float* __restrict__ gb, float* __restrict__ Y)
{
    extern __shared__ __align__(16) float sm[];
    const int tid  = threadIdx.x;
    const int lane = tid & 31;
    const int warp = tid >> 5;
    const int gid  = lane >> 2;
    const int tig  = lane & 3;
    const int wr   = warp >> 2;          // 0..1
    const int wc   = warp & 3;           // 0..3
    const int rowBase = wr * 64;
    const int colBase = wc * 64;
    const int R0 = blockIdx.y * 128;
    const int C0 = blockIdx.x * 256;

    sm[OFF_BIAS + tid] = bias[C0 + tid];
    sm[OFF_GW   + tid] = gw  [C0 + tid];
    sm[OFF_GB   + tid] = gb  [C0 + tid];

    const uint32_t smBase = smem_u32(sm);
    const uint32_t aSm = smBase + OFF_A * 4;
    const uint32_t bSm = smBase + OFF_B * 4;

    const float* Xb = X  + (size_t)R0 * E_;
    const float* Wb = Wr + C0;

#define PB_LOAD(k0, st) do {                                                   \
        const uint32_t aT = aSm + (st) * (A_STAGE * 4);                        \
        const uint32_t bT = bSm + (st) * (B_STAGE * 4);                        \
        { int idx = tid;       int r = idx >> 2, s = idx & 3;                  \
          CP_ASYNC16(aT + r*80 + s*16, Xb + (size_t)r * E_ + (k0) + s*4); }    \
        { int idx = tid + 256; int r = idx >> 2, s = idx & 3;                  \
          CP_ASYNC16(aT + r*80 + s*16, Xb + (size_t)r * E_ + (k0) + s*4); }    \
        _Pragma("unroll")                                                      \
        for (int t = 0; t < 4; t++) {                                          \
            int idx = tid + t*256; int r = idx >> 6, cs = idx & 63;            \
            CP_ASYNC16(bT + r*1056 + cs*16,                                    \
                       Wb + (size_t)((k0) + r) * E_ + cs*4);                   \
        } } while (0)

    float acc[4][8][4];
#pragma unroll
    for (int mt = 0; mt < 4; mt++)
#pragma unroll
        for (int nt = 0; nt < 8; nt++)
#pragma unroll
            for (int c = 0; c < 4; c++) acc[mt][nt][c] = 0.f;

    PB_LOAD(0, 0); CP_COMMIT();

    for (int ch = 0; ch < 64; ch++) {
        if (ch < 63) {
            PB_LOAD((ch + 1) * 16, (ch + 1) & 1);
            CP_COMMIT();
            asm volatile("cp.async.wait_group 1;" ::: "memory");
        } else {
            asm volatile("cp.async.wait_group 0;" ::: "memory");
        }
        __syncthreads();

        const float* As = sm + OFF_A + (ch & 1) * A_STAGE;
        const float* Bs = sm + OFF_B + (ch & 1) * B_STAGE;
#pragma unroll
        for (int kk = 0; kk < 16; kk += 8) {
            unsigned af[4][4], bf[8][2];
#pragma unroll
            for (int mt = 0; mt < 4; mt++) {
                const int r = rowBase + mt * 16 + gid;
                af[mt][0] = __float_as_uint(As[ r      * A_STRIDE + kk + tig    ]);
                af[mt][1] = __float_as_uint(As[(r + 8) * A_STRIDE + kk + tig    ]);
                af[mt][2] = __float_as_uint(As[ r      * A_STRIDE + kk + tig + 4]);
                af[mt][3] = __float_as_uint(As[(r + 8) * A_STRIDE + kk + tig + 4]);
            }
#pragma unroll
            for (int nt = 0; nt < 8; nt++) {
                const int cb = colBase + nt * 8 + gid;
                bf[nt][0] = __float_as_uint(Bs[(kk + tig    ) * B_STRIDE + cb]);
                bf[nt][1] = __float_as_uint(Bs[(kk + tig + 4) * B_STRIDE + cb]);
            }
#pragma unroll
            for (int mt = 0; mt < 4; mt++)
#pragma unroll
                for (int nt = 0; nt < 8; nt++)
                    MMA_TF32(acc[mt][nt], af[mt], bf[nt]);
        }
        __syncthreads();
    }
#undef PB_LOAD

    // ---------------- epilogue: bias + celu + GroupNorm ----------------
    float bv[16], gv[16], g2[16];
#pragma unroll
    for (int nt = 0; nt < 8; nt++)
#pragma unroll
        for (int cc = 0; cc < 2; cc++) {
            const int cl = colBase + nt * 8 + tig * 2 + cc;
            bv[nt*2+cc] = sm[OFF_BIAS + cl];
            gv[nt*2+cc] = sm[OFF_GW   + cl];
            g2[nt*2+cc] = sm[OFF_GB   + cl];
        }

#pragma unroll
    for (int mt = 0; mt < 4; mt++)
#pragma unroll
        for (int nt = 0; nt < 8; nt++)
#pragma unroll
            for (int c = 0; c < 4; c++) {
                float x = acc[mt][nt][c] + bv[nt*2 + (c & 1)];
                acc[mt][nt][c] = (x > 0.f) ? x : CELU_ALPHA * expm1f(x * (1.f / CELU_ALPHA));
            }

    float* redS = sm + OFF_REDS;
    float* redQ = sm + OFF_REDQ;
#pragma unroll
    for (int mt = 0; mt < 4; mt++) {
        float s0 = 0.f, q0 = 0.f, s1 = 0.f, q1 = 0.f;
#pragma unroll
        for (int nt = 0; nt < 8; nt++) {
            float v;
            v = acc[mt][nt][0]; s0 += v; q0 += v * v;
            v = acc[mt][nt][1]; s0 += v; q0 += v * v;
            v = acc[mt][nt][2]; s1 += v; q1 += v * v;
            v = acc[mt][nt][3]; s1 += v; q1 += v * v;
        }
        s0 += __shfl_xor_sync(0xffffffffu, s0, 1); s0 += __shfl_xor_sync(0xffffffffu, s0, 2);
        q0 += __shfl_xor_sync(0xffffffffu, q0, 1); q0 += __shfl_xor_sync(0xffffffffu, q0, 2);
        s1 += __shfl_xor_sync(0xffffffffu, s1, 1); s1 += __shfl_xor_sync(0xffffffffu, s1, 2);
        q1 += __shfl_xor_sync(0xffffffffu, q1, 1); q1 += __shfl_xor_sync(0xffffffffu, q1, 2);
        if (tig == 0) {
            const int r = rowBase + mt * 16 + gid;
            redS[wc * 128 + r]     = s0; redQ[wc * 128 + r]     = q0;
            redS[wc * 128 + r + 8] = s1; redQ[wc * 128 + r + 8] = q1;
        }
    }
    __syncthreads();

    const int pg = wc & 2;   // col-warp pair base for this warp's GN group
#pragma unroll
    for (int mt = 0; mt < 4; mt++)
#pragma unroll
        for (int hf = 0; hf < 2; hf++) {
            const int r = rowBase + mt * 16 + gid + hf * 8;
            const float mu  = (redS[pg*128 + r] + redS[(pg+1)*128 + r]) * (1.f / 128.f);
            const float var = (redQ[pg*128 + r] + redQ[(pg+1)*128 + r]) * (1.f / 128.f) - mu * mu;
            const float inv = rsqrtf(var + EPS_);
            float* yr = Y + (size_t)(R0 + r) * E_ + C0 + colBase + tig * 2;
#pragma unroll
            for (int nt = 0; nt < 8; nt++) {
                float2 o;
                o.x = (acc[mt][nt][hf*2+0] - mu) * inv * gv[nt*2+0] + g2[nt*2+0];
                o.y = (acc[mt][nt][hf*2+1] - mu) * inv * gv[nt*2+1] + g2[nt*2+1];
                *(float2*)(yr + nt * 8) = o;
            }
        }
}

// =============================================================================
// SMALL fused projection (256 rows): block tile 32x128, grid (8,8)=64 blocks.
// 8 warps: 2 row-warps x 4 col-warps, warp tile 16x32.
// =============================================================================
__global__ void __launch_bounds__(256)
proj_small(const float* __restrict__ X, const float* __restrict__ W,
           const float* __restrict__ bias, const float* __restrict__ gw,
           const float* __restrict__ gb, float* __restrict__ Y)
{
    __shared__ __align__(16) float As[2][16][40];    // [k][row(32)+pad]
    __shared__ __align__(16) float Bs[2][16][136];   // [k][col(128)+pad]
    __shared__ float redS[4][32], redQ[4][32];

    const int tid  = threadIdx.x;
    const int lane = tid & 31;
    const int warp = tid >> 5;
    const int gid  = lane >> 2;
    const int tig  = lane & 3;
    const int wr   = warp & 1;           // 0..1
    const int wc   = warp >> 1;          // 0..3
    const int rowBase = wr * 16;
    const int colBase = wc * 32;
    const int R0 = blockIdx.y * 32;
    const int C0 = blockIdx.x * 128;

    const int rowA = tid >> 2, segA = tid & 3;           // tid<128 loads A
    const int bk   = tid >> 4, bcol = (tid & 15) * 4;    // B loader (as R7)

    const float* Ap = X + (size_t)(R0 + rowA) * E_ + segA * 4;
    const float* Bp = W + (size_t)bk * E_ + C0 + bcol;

    float acc[4][4];
#pragma unroll
    for (int nt = 0; nt < 4; nt++)
#pragma unroll
        for (int c = 0; c < 4; c++) acc[nt][c] = 0.f;

    float4 pa, pb0, pb1;
    if (tid < 128) pa = *(const float4*)(Ap);
    pb0 = *(const float4*)(Bp);
    pb1 = *(const float4*)(Bp + 64);
    if (tid < 128) {
        As[0][segA*4+0][rowA] = tf32r(pa.x); As[0][segA*4+1][rowA] = tf32r(pa.y);
        As[0][segA*4+2][rowA] = tf32r(pa.z); As[0][segA*4+3][rowA] = tf32r(pa.w);
    }
    {
        float4 t0 = make_float4(tf32r(pb0.x), tf32r(pb0.y), tf32r(pb0.z), tf32r(pb0.w));
        float4 t1 = make_float4(tf32r(pb1.x), tf32r(pb1.y), tf32r(pb1.z), tf32r(pb1.w));
        *(float4*)&Bs[0][bk][bcol]      = t0;
        *(float4*)&Bs[0][bk][bcol + 64] = t1;
    }
    __syncthreads();

    for (int ch = 0; ch < 64; ch++) {
        const int cur = ch & 1;
        if (ch < 63) {
            const int k0 = (ch + 1) * 16;
            if (tid < 128) pa = *(const float4*)(Ap + k0);
            pb0 = *(const float4*)(Bp + (size_t)k0 * E_);
            pb1 = *(const float4*)(Bp + (size_t)k0 * E_ + 64);
        }
#pragma unroll
        for (int kk = 0; kk < 16; kk += 8) {
            unsigned af[4], bf[4][2];
            af[0] = __float_as_uint(As[cur][kk+tig  ][rowBase+gid  ]);
            af[1] = __float_as_uint(As[cur][kk+tig  ][rowBase+gid+8]);
            af[2] = __float_as_uint(As[cur][kk+tig+4][rowBase+gid  ]);
            af[3] = __float_as_uint(As[cur][kk+tig+4][rowBase+gid+8]);
#pragma unroll
            for (int nt = 0; nt < 4; nt++) {
                const int cb = colBase + nt * 8 + gid;
                bf[nt][0] = __float_as_uint(Bs[cur][kk+tig  ][cb]);
                bf[nt][1] = __float_as_uint(Bs[cur][kk+tig+4][cb]);
            }
#pragma unroll
            for (int nt = 0; nt < 4; nt++)
                MMA_TF32(acc[nt], af, bf[nt]);
        }
        if (ch < 63) {
            const int nxt = cur ^ 1;
            if (tid < 128) {
                As[nxt][segA*4+0][rowA] = tf32r(pa.x); As[nxt][segA*4+1][rowA] = tf32r(pa.y);
                As[nxt][segA*4+2][rowA] = tf32r(pa.z); As[nxt][segA*4+3][rowA] = tf32r(pa.w);
            }
            float4 t0 = make_float4(tf32r(pb0.x), tf32r(pb0.y), tf32r(pb0.z), tf32r(pb0.w));
            float4 t1 = make_float4(tf32r(pb1.x), tf32r(pb1.y), tf32r(pb1.z), tf32r(pb1.w));
            *(float4*)&Bs[nxt][bk][bcol]      = t0;
            *(float4*)&Bs[nxt][bk][bcol + 64] = t1;
        }
        __syncthreads();
    }

    // epilogue
    float bv[8], gv[8], g2[8];
#pragma unroll
    for (int nt = 0; nt < 4; nt++)
#pragma unroll
        for (int cc = 0; cc < 2; cc++) {
            const int cg = C0 + colBase + nt * 8 + tig * 2 + cc;
            bv[nt*2+cc] = bias[cg];
            gv[nt*2+cc] = gw[cg];
            g2[nt*2+cc] = gb[cg];
        }
#pragma unroll
    for (int nt = 0; nt < 4; nt++)
#pragma unroll
        for (int c = 0; c < 4; c++) {
            float x = acc[nt][c] + bv[nt*2 + (c & 1)];
            acc[nt][c] = (x > 0.f) ? x : CELU_ALPHA * expm1f(x * (1.f / CELU_ALPHA));
        }
    {
        float s0 = 0.f, q0 = 0.f, s1 = 0.f, q1 = 0.f;
#pragma unroll
        for (int nt = 0; nt < 4; nt++) {
            float v;
            v = acc[nt][0]; s0 += v; q0 += v * v;
            v = acc[nt][1]; s0 += v; q0 += v * v;
            v = acc[nt][2]; s1 += v; q1 += v * v;
            v = acc[nt][3]; s1 += v; q1 += v * v;
        }
        s0 += __shfl_xor_sync(0xffffffffu, s0, 1); s0 += __shfl_xor_sync(0xffffffffu, s0, 2);
        q0 += __shfl_xor_sync(0xffffffffu, q0, 1); q0 += __shfl_xor_sync(0xffffffffu, q0, 2);
        s1 += __shfl_xor_sync(0xffffffffu, s1, 1); s1 += __shfl_xor_sync(0xffffffffu, s1, 2);
        q1 += __shfl_xor_sync(0xffffffffu, q1, 1); q1 += __shfl_xor_sync(0xffffffffu, q1, 2);
        if (tig == 0) {
            redS[wc][rowBase+gid]   = s0; redQ[wc][rowBase+gid]   = q0;
            redS[wc][rowBase+gid+8] = s1; redQ[wc][rowBase+gid+8] = q1;
        }
    }
    __syncthreads();

#pragma unroll
    for (int hf = 0; hf < 2; hf++) {
        const int r = rowBase + gid + hf * 8;
        const float s = redS[0][r] + redS[1][r] + redS[2][r] + redS[3][r];
        const float q = redQ[0][r] + redQ[1][r] + redQ[2][r] + redQ[3][r];
        const float mu  = s * (1.f / 128.f);
        const float var = q * (1.f / 128.f) - mu * mu;
        const float inv = rsqrtf(var + EPS_);
        float* yr = Y + (size_t)(R0 + r) * E_ + C0 + colBase + tig * 2;
#pragma unroll
        for (int nt = 0; nt < 4; nt++) {
            float2 o;
            o.x = (acc[nt][hf*2+0] - mu) * inv * gv[nt*2+0] + g2[nt*2+0];
            o.y = (acc[nt][hf*2+1] - mu) * inv * gv[nt*2+1] + g2[nt*2+1];
            *(float2*)(yr + nt * 8) = o;
        }
    }
}

// =============================================================================
// Attention stage: one block per (b, h), 256 threads. Pass-1 uses 4-row
// m-chunks so each WbqT float4 is reused across 4 rows (3x less crossbar).
// WbqT + kbuf live in dynamic smem (50176 B).
// =============================================================================
#define ATTN_DYN ((64*132 + 8*4*128) * 4)

__global__ void __launch_bounds__(256)
attn_kernel(const float* __restrict__ q,  const float* __restrict__ v1,
            const float* __restrict__ k,  const float* __restrict__ v2,
            const int*   __restrict__ mask,
            const float* __restrict__ Wb, const float* __restrict__ bb,
            const float* __restrict__ Ws, const float* __restrict__ bs,
            const float* __restrict__ Wc, const float* __restrict__ bc,
            float* __restrict__ out)
{
    extern __shared__ __align__(16) float dyn[];
    float* WbqT  = dyn;               // [64][132]
    float* kbufA = dyn + 64 * 132;    // [8][4][128]

    __shared__ float score[M_];
    __shared__ float wts[M_];
    __shared__ float maskf_s[M_];
    __shared__ float poolPart[8][MID_];
    __shared__ float pool[MID_];
    __shared__ float bbS[MID_], WsS[MID_];
    __shared__ float redA[8], redB[8], redC[8];
    __shared__ float v2part[2][DH];
    __shared__ float sMsInv, sMax, sSInv;

    const int tid  = threadIdx.x;
    const int lane = tid & 31;
    const int w    = tid >> 5;
    const int b    = blockIdx.x >> 3;
    const int h    = blockIdx.x & 7;

    const float* qp = q + (size_t)b * E_ + h * DH;

    for (int i = tid; i < DH * MID_; i += 256) {
        const int d = i >> 6, j = i & 63;
        WbqT[j * 132 + d] = qp[d] * Wb[i];
    }
    if (tid < MID_) { bbS[tid] = bb[tid]; WsS[tid] = Ws[tid]; }
    for (int i = tid; i < M_; i += 256) maskf_s[i] = (float)mask[(size_t)b * M_ + i];
    __syncthreads();

    // ---- pass 1: hidden GEMM (4-row chunks), score, pool in registers ----
    const int j0 = lane, j1 = lane + 32;
    const float* kbase = k + (size_t)b * M_ * E_ + h * DH;
    float* kb = kbufA + w * 4 * 128;
    float pp0 = 0.f, pp1 = 0.f;

    for (int c = w; c < 49; c += 8) {
        const int mb = c * 4;
#pragma unroll
        for (int r = 0; r < 4; r++)
            ((float4*)(kb + r * 128))[lane] =
                ((const float4*)(kbase + (size_t)(mb + r) * E_))[lane];
        __syncwarp();

        float a[4][2];
#pragma unroll
        for (int r = 0; r < 4; r++) { a[r][0] = bbS[j0]; a[r][1] = bbS[j1]; }
#pragma unroll
        for (int d = 0; d < DH; d += 4) {
            const float4 w0 = *(const float4*)(WbqT + j0 * 132 + d);
            const float4 w1 = *(const float4*)(WbqT + j1 * 132 + d);
#pragma unroll
            for (int r = 0; r < 4; r++) {
                const float4 av = *(const float4*)(kb + r * 128 + d);
                a[r][0] += av.x * w0.x + av.y * w0.y + av.z * w0.z + av.w * w0.w;
                a[r][1] += av.x * w1.x + av.y * w1.y + av.z * w1.z + av.w * w1.w;
            }
        }
#pragma unroll
        for (int r = 0; r < 4; r++) {
            const float h0 = fmaxf(a[r][0], 0.f), h1 = fmaxf(a[r][1], 0.f);
            const float mf = maskf_s[mb + r];
            pp0 += h0 * mf;
            pp1 += h1 * mf;
            float p = h0 * WsS[j0] + h1 * WsS[j1];
#pragma unroll
            for (int o = 16; o > 0; o >>= 1) p += __shfl_xor_sync(0xffffffffu, p, o);
            if (lane == 0) score[mb + r] = p;
        }
        __syncwarp();
    }
    poolPart[w][j0] = pp0;
    poolPart[w][j1] = pp1;
    __syncthreads();

    if (tid < MID_) {
        float s = 0.f;
#pragma unroll
        for (int ww = 0; ww < 8; ww++) s += poolPart[ww][tid];
        pool[tid] = s;
    }
    {
        float ms = 0.f;
        for (int i = tid; i < M_; i += 256) ms += maskf_s[i];
#pragma unroll
        for (int o = 16; o > 0; o >>= 1) ms += __shfl_xor_sync(0xffffffffu, ms, o);
        if (lane == 0) redA[w] = ms;
    }
    __syncthreads();
    if (tid == 0) {
        float t = 0.f;
#pragma unroll
        for (int ww = 0; ww < 8; ww++) t += redA[ww];
        sMsInv = 1.f / t;
    }

    const float bs0 = bs[0];
    {
        float mx = -1e30f;
        for (int i = tid; i < M_; i += 256) {
            float s = (maskf_s[i] != 0.f) ? (score[i] + bs0) : -1e9f;
            score[i] = s;
            mx = fmaxf(mx, s);
        }
#pragma unroll
        for (int o = 16; o > 0; o >>= 1) mx = fmaxf(mx, __shfl_xor_sync(0xffffffffu, mx, o));
        if (lane == 0) redB[w] = mx;
    }
    __syncthreads();
    if (tid == 0) {
        float mx = -1e30f;
#pragma unroll
        for (int ww = 0; ww < 8; ww++) mx = fmaxf(mx, redB[ww]);
        sMax = mx;
    }
    __syncthreads();

    {
        const float mx = sMax;
        float se = 0.f;
        for (int i = tid; i < M_; i += 256) {
            float e = expf(score[i] - mx);
            wts[i] = e;
            se += e;
        }
#pragma unroll
        for (int o = 16; o > 0; o >>= 1) se += __shfl_xor_sync(0xffffffffu, se, o);
        if (lane == 0) redC[w] = se;
    }
    __syncthreads();
    if (tid == 0) {
        float t = 0.f;
#pragma unroll
        for (int ww = 0; ww < 8; ww++) t += redC[ww];
        sSInv = 1.f / t;
    }
    __syncthreads();

    {
        const int half = tid >> 7;
        const int d    = tid & 127;
        const float* v2base = v2 + (size_t)b * M_ * E_ + h * DH + d;
        float accv = 0.f;
        for (int m = half; m < M_; m += 2)
            accv += wts[m] * v2base[(size_t)m * E_];
        v2part[half][d] = accv;
    }
    __syncthreads();

    if (tid < DH) {
        const int d = tid;
        const float v2p = (v2part[0][d] + v2part[1][d]) * sSInv;
        const float msInv = sMsInv;
        float ac = bc[d];
#pragma unroll
        for (int j = 0; j < MID_; j++)
            ac += (pool[j] * msInv) * Wc[j * DH + d];
        const float sig = 1.f / (1.f + expf(-ac));
        out[(size_t)b * E_ + h * DH + d] = v1[(size_t)b * E_ + h * DH + d] * v2p * sig;
    }
}

// =============================================================================
// launch
// =============================================================================
extern "C" void kernel_launch(void* const* d_in, const int* in_sizes, int n_in,
                              void* d_out, int out_size)
{
    (void)in_sizes; (void)n_in; (void)out_size;
    const float* query  = (const float*)d_in[0];
    const float* key    = (const float*)d_in[1];
    const int*   mask   = (const int*  )d_in[2];
    const float* value1 = (const float*)d_in[3];
    const float* value2 = (const float*)d_in[4];
    const float* Wq = (const float*)d_in[5];
    const float* bq = (const float*)d_in[6];
    const float* gqw = (const float*)d_in[7];
    const float* gqb = (const float*)d_in[8];
    const float* Wk = (const float*)d_in[9];
    const float* bk = (const float*)d_in[10];
    const float* gkw = (const float*)d_in[11];
    const float* gkb = (const float*)d_in[12];
    const float* Wv1 = (const float*)d_in[13];
    const float* bv1 = (const float*)d_in[14];
    const float* gv1w = (const float*)d_in[15];
    const float* gv1b = (const float*)d_in[16];
    const float* Wv2 = (const float*)d_in[17];
    const float* bv2 = (const float*)d_in[18];
    const float* gv2w = (const float*)d_in[19];
    const float* gv2b = (const float*)d_in[20];
    const float* Wb = (const float*)d_in[21];
    const float* bb = (const float*)d_in[22];
    const float* Ws = (const float*)d_in[23];
    const float* bs = (const float*)d_in[24];
    const float* Wc = (const float*)d_in[25];
    const float* bc = (const float*)d_in[26];
    float* out = (float*)d_out;

    float *dq, *dv1, *dk, *dv2, *dWkr, *dWv2r;
    cudaGetSymbolAddress((void**)&dq,    g_q);
    cudaGetSymbolAddress((void**)&dv1,   g_v1);
    cudaGetSymbolAddress((void**)&dk,    g_k);
    cudaGetSymbolAddress((void**)&dv2,   g_v2);
    cudaGetSymbolAddress((void**)&dWkr,  g_Wkr);
    cudaGetSymbolAddress((void**)&dWv2r, g_Wv2r);

    cudaFuncSetAttribute(proj_big, cudaFuncAttributeMaxDynamicSharedMemorySize, PB_DYN);
    cudaFuncSetAttribute(attn_kernel, cudaFuncAttributeMaxDynamicSharedMemorySize, ATTN_DYN);

    dim3 blk(256);
    // pre-round weights (rna) for the big projections
    round_w<<<1024, blk>>>(Wk,  dWkr);
    round_w<<<1024, blk>>>(Wv2, dWv2r);
    // small projections (256 rows): 32x128 tiles, 64 blocks
    proj_small<<<dim3(8, 8), blk>>>(query,  Wq,  bq,  gqw,  gqb,  dq);
    proj_small<<<dim3(8, 8), blk>>>(value1, Wv1, bv1, gv1w, gv1b, dv1);
    // big projections: 128x256 tiles
    proj_big<<<dim3(4, NKV/128), blk, PB_DYN>>>(key,    dWkr,  bk,  gkw,  gkb,  dk);
    proj_big<<<dim3(4, NKV/128), blk, PB_DYN>>>(value2, dWv2r, bv2, gv2w, gv2b, dv2);
    // attention stage
    attn_kernel<<<dim3(B_*H_), blk, ATTN_DYN>>>(dq, dv1, dk, dv2, mask,
                                                Wb, bb, Ws, bs, Wc, bc, out);
}

// round 11
// speedup vs baseline: 1.3604x; 1.2012x over previous
#include <cuda_runtime.h>
#include <math.h>
#include <stdint.h>

// Problem constants
#define B_   256
#define M_   196
#define E_   1024
#define H_   8
#define DH   128
#define MID_ 64
#define NKV  (B_*M_)
#define CELU_ALPHA 1.3f
#define EPS_ 1e-5f

// ---------------- scratch (device globals; no allocation allowed) -------------
__device__ float g_q  [B_*E_];
__device__ float g_v1 [B_*E_];
__device__ float g_k  [NKV*E_];
__device__ float g_v2 [NKV*E_];
__device__ float g_Wqr [E_*E_];
__device__ float g_Wv1r[E_*E_];
__device__ float g_Wkr [E_*E_];
__device__ float g_Wv2r[E_*E_];

// ---------------- helpers ----------------------------------------------------
static __device__ __forceinline__ float tf32r(float x) {
    unsigned u;
    asm("cvt.rna.tf32.f32 %0, %1;" : "=r"(u) : "f"(x));
    return __uint_as_float(u);
}
static __device__ __forceinline__ uint32_t smem_u32(const void* p) {
    uint32_t a;
    asm("{ .reg .u64 t; cvta.to.shared.u64 t, %1; cvt.u32.u64 %0, t; }" : "=r"(a) : "l"(p));
    return a;
}
#define CP_ASYNC16(dst, src) \
    asm volatile("cp.async.cg.shared.global [%0], [%1], 16;" :: "r"(dst), "l"(src))
#define CP_COMMIT() asm volatile("cp.async.commit_group;" ::: "memory")

#define MMA_TF32(acc, af, bf)                                                   \
    asm volatile(                                                               \
        "mma.sync.aligned.m16n8k8.row.col.f32.tf32.tf32.f32 "                   \
        "{%0,%1,%2,%3}, {%4,%5,%6,%7}, {%8,%9}, {%0,%1,%2,%3};\n"               \
        : "+f"((acc)[0]), "+f"((acc)[1]), "+f"((acc)[2]), "+f"((acc)[3])        \
        : "r"((af)[0]), "r"((af)[1]), "r"((af)[2]), "r"((af)[3]),               \
          "r"((bf)[0]), "r"((bf)[1]))

// =============================================================================
// tf32-rna round of all 4 weight matrices. grid (1024, 4), 256 thr.
// =============================================================================
__global__ void __launch_bounds__(256)
round_w4(const float* __restrict__ s0, const float* __restrict__ s1,
         const float* __restrict__ s2, const float* __restrict__ s3,
         float* __restrict__ d0, float* __restrict__ d1,
         float* __restrict__ d2, float* __restrict__ d3)
{
    const float* S; float* D;
    switch (blockIdx.y) {
        case 0:  S = s0; D = d0; break;
        case 1:  S = s1; D = d1; break;
        case 2:  S = s2; D = d2; break;
        default: S = s3; D = d3; break;
    }
    const int i = blockIdx.x * 256 + threadIdx.x;
    float4 v = ((const float4*)S)[i];
    ((float4*)D)[i] = make_float4(tf32r(v.x), tf32r(v.y), tf32r(v.z), tf32r(v.w));
}

// =============================================================================
// BIG fused projection (k + v2 merged via blockIdx.z):
//   Y = GroupNorm(celu(X @ W + b)) * gw + gb
// Block tile 128x128, 8 warps (2 row x 4 col), warp tile 64x32.
// cp.async double buffer, static smem 43.5KB, 2 CTAs/SM.
// Grid: (8, nrows/128, 2). GN group (128 ch) == the 128-col tile.
// =============================================================================
#define PBA_STR 20
#define PBB_STR 136
#define PBA_ST  (128*PBA_STR)     // 2560 floats / stage
#define PBB_ST  (16*PBB_STR)      // 2176 floats / stage

__global__ void __launch_bounds__(256, 2)
proj_big(const float* __restrict__ X0, const float* __restrict__ W0,
         const float* __restrict__ b0, const float* __restrict__ g0,
         const float* __restrict__ q0, float* __restrict__ Y0,
         const float* __restrict__ X1, const float* __restrict__ W1,
         const float* __restrict__ b1, const float* __restrict__ g1,
         const float* __restrict__ q1, float* __restrict__ Y1)
{
    __shared__ __align__(16) float As[2 * PBA_ST];
    __shared__ __align__(16) float Bs[2 * PBB_ST];
    __shared__ float sPar[3 * 128];
    __shared__ float redS[4][128], redQ[4][128];

    const float *X, *W, *bias, *gw, *gb; float* Y;
    if (blockIdx.z == 0) { X = X0; W = W0; bias = b0; gw = g0; gb = q0; Y = Y0; }
    else                 { X = X1; W = W1; bias = b1; gw = g1; gb = q1; Y = Y1; }

    const int tid  = threadIdx.x;
    const int lane = tid & 31;
    const int warp = tid >> 5;
    const int gid  = lane >> 2;
    const int tig  = lane & 3;
    const int wr   = warp >> 2;          // 0..1
    const int wc   = warp & 3;           // 0..3
    const int rowBase = wr * 64;
    const int colBase = wc * 32;
    const int R0 = blockIdx.y * 128;
    const int C0 = blockIdx.x * 128;

    if (tid < 128) {
        sPar[tid]       = bias[C0 + tid];
        sPar[128 + tid] = gw  [C0 + tid];
        sPar[256 + tid] = gb  [C0 + tid];
    }

    const uint32_t aSm = smem_u32(As);
    const uint32_t bSm = smem_u32(Bs);
    const float* Xb = X + (size_t)R0 * E_;
    const float* Wb = W + C0;

    // per-chunk loads: A 128x16 (2 f4/thread), B 16x128 (2 f4/thread)
    const int ar = tid >> 2, as_ = tid & 3;         // A: rows 0..63 (+64 on 2nd)
    const int br = tid >> 5, bc = tid & 31;         // B: rows 0..7  (+8  on 2nd)

#define PB_LOAD(k0, st) do {                                                   \
        const uint32_t aT = aSm + (st) * (PBA_ST * 4);                         \
        const uint32_t bT = bSm + (st) * (PBB_ST * 4);                         \
        CP_ASYNC16(aT + ar*80 + as_*16,        Xb + (size_t)ar * E_ + (k0) + as_*4);        \
        CP_ASYNC16(aT + (ar+64)*80 + as_*16,   Xb + (size_t)(ar+64) * E_ + (k0) + as_*4);   \
        CP_ASYNC16(bT + br*544 + bc*16,        Wb + (size_t)((k0) + br) * E_ + bc*4);       \
        CP_ASYNC16(bT + (br+8)*544 + bc*16,    Wb + (size_t)((k0) + br + 8) * E_ + bc*4);   \
    } while (0)

    float acc[4][4][4];
#pragma unroll
    for (int mt = 0; mt < 4; mt++)
#pragma unroll
        for (int nt = 0; nt < 4; nt++)
#pragma unroll
            for (int c = 0; c < 4; c++) acc[mt][nt][c] = 0.f;

    PB_LOAD(0, 0); CP_COMMIT();

    for (int ch = 0; ch < 64; ch++) {
        if (ch < 63) {
            PB_LOAD((ch + 1) * 16, (ch + 1) & 1);
            CP_COMMIT();
            asm volatile("cp.async.wait_group 1;" ::: "memory");
        } else {
            asm volatile("cp.async.wait_group 0;" ::: "memory");
        }
        __syncthreads();

        const float* Ap = As + (ch & 1) * PBA_ST;
        const float* Bp = Bs + (ch & 1) * PBB_ST;
#pragma unroll
        for (int kk = 0; kk < 16; kk += 8) {
            unsigned af[4][4], bf[4][2];
#pragma unroll
            for (int mt = 0; mt < 4; mt++) {
                const int r = rowBase + mt * 16 + gid;
                af[mt][0] = __float_as_uint(Ap[ r      * PBA_STR + kk + tig    ]);
                af[mt][1] = __float_as_uint(Ap[(r + 8) * PBA_STR + kk + tig    ]);
                af[mt][2] = __float_as_uint(Ap[ r      * PBA_STR + kk + tig + 4]);
                af[mt][3] = __float_as_uint(Ap[(r + 8) * PBA_STR + kk + tig + 4]);
            }
#pragma unroll
            for (int nt = 0; nt < 4; nt++) {
                const int cb = colBase + nt * 8 + gid;
                bf[nt][0] = __float_as_uint(Bp[(kk + tig    ) * PBB_STR + cb]);
                bf[nt][1] = __float_as_uint(Bp[(kk + tig + 4) * PBB_STR + cb]);
            }
#pragma unroll
            for (int mt = 0; mt < 4; mt++)
#pragma unroll
                for (int nt = 0; nt < 4; nt++)
                    MMA_TF32(acc[mt][nt], af[mt], bf[nt]);
        }
        __syncthreads();
    }
#undef PB_LOAD

    // ---------------- epilogue: bias + celu + GroupNorm ----------------
    float bv[8], gv[8], g2[8];
#pragma unroll
    for (int nt = 0; nt < 4; nt++)
#pragma unroll
        for (int cc = 0; cc < 2; cc++) {
            const int cl = colBase + nt * 8 + tig * 2 + cc;
            bv[nt*2+cc] = sPar[cl];
            gv[nt*2+cc] = sPar[128 + cl];
            g2[nt*2+cc] = sPar[256 + cl];
        }

#pragma unroll
    for (int mt = 0; mt < 4; mt++)
#pragma unroll
        for (int nt = 0; nt < 4; nt++)
#pragma unroll
            for (int c = 0; c < 4; c++) {
                float x = acc[mt][nt][c] + bv[nt*2 + (c & 1)];
                acc[mt][nt][c] = (x > 0.f) ? x : CELU_ALPHA * expm1f(x * (1.f / CELU_ALPHA));
            }

#pragma unroll
    for (int mt = 0; mt < 4; mt++) {
        float s0 = 0.f, q0v = 0.f, s1 = 0.f, q1v = 0.f;
#pragma unroll
        for (int nt = 0; nt < 4; nt++) {
            float v;
            v = acc[mt][nt][0]; s0 += v; q0v += v * v;
            v = acc[mt][nt][1]; s0 += v; q0v += v * v;
            v = acc[mt][nt][2]; s1 += v; q1v += v * v;
            v = acc[mt][nt][3]; s1 += v; q1v += v * v;
        }
        s0  += __shfl_xor_sync(0xffffffffu, s0, 1);  s0  += __shfl_xor_sync(0xffffffffu, s0, 2);
        q0v += __shfl_xor_sync(0xffffffffu, q0v, 1); q0v += __shfl_xor_sync(0xffffffffu, q0v, 2);
        s1  += __shfl_xor_sync(0xffffffffu, s1, 1);  s1  += __shfl_xor_sync(0xffffffffu, s1, 2);
        q1v += __shfl_xor_sync(0xffffffffu, q1v, 1); q1v += __shfl_xor_sync(0xffffffffu, q1v, 2);
        if (tig == 0) {
            const int r = rowBase + mt * 16 + gid;
            redS[wc][r]     = s0; redQ[wc][r]     = q0v;
            redS[wc][r + 8] = s1; redQ[wc][r + 8] = q1v;
        }
    }
    __syncthreads();

#pragma unroll
    for (int mt = 0; mt < 4; mt++)
#pragma unroll
        for (int hf = 0; hf < 2; hf++) {
            const int r = rowBase + mt * 16 + gid + hf * 8;
            const float s = redS[0][r] + redS[1][r] + redS[2][r] + redS[3][r];
            const float q = redQ[0][r] + redQ[1][r] + redQ[2][r] + redQ[3][r];
            const float mu  = s * (1.f / 128.f);
            const float var = q * (1.f / 128.f) - mu * mu;
            const float inv = rsqrtf(var + EPS_);
            float* yr = Y + (size_t)(R0 + r) * E_ + C0 + colBase + tig * 2;
#pragma unroll
            for (int nt = 0; nt < 4; nt++) {
                float2 o;
                o.x = (acc[mt][nt][hf*2+0] - mu) * inv * gv[nt*2+0] + g2[nt*2+0];
                o.y = (acc[mt][nt][hf*2+1] - mu) * inv * gv[nt*2+1] + g2[nt*2+1];
                *(float2*)(yr + nt * 8) = o;
            }
        }
}

// =============================================================================
// SMALL fused projection (q + v1 merged via blockIdx.z), 256 rows each.
// Block tile 32x128, grid (8,8,2). 3-stage cp.async pipeline.
// 8 warps: 2 row x 4 col, warp tile 16x32.
// =============================================================================
#define PSA_ST 640                 // 32*20 floats
#define PSB_ST 2176                // 16*136 floats
#define PS_ST  (PSA_ST + PSB_ST)   // 2816 floats / stage

__global__ void __launch_bounds__(256)
proj_small(const float* __restrict__ X0, const float* __restrict__ W0,
           const float* __restrict__ b0, const float* __restrict__ g0,
           const float* __restrict__ q0, float* __restrict__ Y0,
           const float* __restrict__ X1, const float* __restrict__ W1,
           const float* __restrict__ b1, const float* __restrict__ g1,
           const float* __restrict__ q1, float* __restrict__ Y1)
{
    __shared__ __align__(16) float sm[3 * PS_ST];
    __shared__ float redS[4][32], redQ[4][32];

    const float *X, *W, *bias, *gw, *gb; float* Y;
    if (blockIdx.z == 0) { X = X0; W = W0; bias = b0; gw = g0; gb = q0; Y = Y0; }
    else                 { X = X1; W = W1; bias = b1; gw = g1; gb = q1; Y = Y1; }

    const int tid  = threadIdx.x;
    const int lane = tid & 31;
    const int warp = tid >> 5;
    const int gid  = lane >> 2;
    const int tig  = lane & 3;
    const int wr   = warp & 1;
    const int wc   = warp >> 1;
    const int rowBase = wr * 16;
    const int colBase = wc * 32;
    const int R0 = blockIdx.y * 32;
    const int C0 = blockIdx.x * 128;

    const uint32_t smB = smem_u32(sm);
    const float* Xb = X + (size_t)R0 * E_;
    const float* Wb = W + C0;

    const int ar = tid >> 2, as_ = tid & 3;   // tid<128: A rows 0..31
    const int br = tid >> 5, bc = tid & 31;   // B rows 0..7 (+8)

#define PS_LOAD(k0, st) do {                                                   \
        const uint32_t aT = smB + (st) * (PS_ST * 4);                          \
        const uint32_t bT = aT + PSA_ST * 4;                                   \
        if (tid < 128)                                                         \
            CP_ASYNC16(aT + ar*80 + as_*16, Xb + (size_t)ar * E_ + (k0) + as_*4); \
        CP_ASYNC16(bT + br*544 + bc*16,     Wb + (size_t)((k0) + br) * E_ + bc*4);       \
        CP_ASYNC16(bT + (br+8)*544 + bc*16, Wb + (size_t)((k0) + br + 8) * E_ + bc*4);   \
    } while (0)

    float acc[4][4];
#pragma unroll
    for (int nt = 0; nt < 4; nt++)
#pragma unroll
        for (int c = 0; c < 4; c++) acc[nt][c] = 0.f;

    PS_LOAD(0, 0);  CP_COMMIT();
    PS_LOAD(16, 1); CP_COMMIT();

    int st = 0;
    for (int ch = 0; ch < 64; ch++) {
        if (ch + 2 < 64) {
            int ls = st + 2; if (ls >= 3) ls -= 3;
            PS_LOAD((ch + 2) * 16, ls);
        }
        CP_COMMIT();
        asm volatile("cp.async.wait_group 2;" ::: "memory");
        __syncthreads();

        const float* Ap = sm + st * PS_ST;
        const float* Bp = Ap + PSA_ST;
#pragma unroll
        for (int kk = 0; kk < 16; kk += 8) {
            unsigned af[4], bf[4][2];
            const int r = rowBase + gid;
            af[0] = __float_as_uint(Ap[ r      * 20 + kk + tig    ]);
            af[1] = __float_as_uint(Ap[(r + 8) * 20 + kk + tig    ]);
            af[2] = __float_as_uint(Ap[ r      * 20 + kk + tig + 4]);
            af[3] = __float_as_uint(Ap[(r + 8) * 20 + kk + tig + 4]);
#pragma unroll
            for (int nt = 0; nt < 4; nt++) {
                const int cb = colBase + nt * 8 + gid;
                bf[nt][0] = __float_as_uint(Bp[(kk + tig    ) * 136 + cb]);
                bf[nt][1] = __float_as_uint(Bp[(kk + tig + 4) * 136 + cb]);
            }
#pragma unroll
            for (int nt = 0; nt < 4; nt++)
                MMA_TF32(acc[nt], af, bf[nt]);
        }
        __syncthreads();
        if (++st == 3) st = 0;
    }
#undef PS_LOAD

    // epilogue
    float bv[8], gv[8], g2[8];
#pragma unroll
    for (int nt = 0; nt < 4; nt++)
#pragma unroll
        for (int cc = 0; cc < 2; cc++) {
            const int cg = C0 + colBase + nt * 8 + tig * 2 + cc;
            bv[nt*2+cc] = bias[cg];
            gv[nt*2+cc] = gw[cg];
            g2[nt*2+cc] = gb[cg];
        }
#pragma unroll
    for (int nt = 0; nt < 4; nt++)
#pragma unroll
        for (int c = 0; c < 4; c++) {
            float x = acc[nt][c] + bv[nt*2 + (c & 1)];
            acc[nt][c] = (x > 0.f) ? x : CELU_ALPHA * expm1f(x * (1.f / CELU_ALPHA));
        }
    {
        float s0 = 0.f, q0v = 0.f, s1 = 0.f, q1v = 0.f;
#pragma unroll
        for (int nt = 0; nt < 4; nt++) {
            float v;
            v = acc[nt][0]; s0 += v; q0v += v * v;
            v = acc[nt][1]; s0 += v; q0v += v * v;
            v = acc[nt][2]; s1 += v; q1v += v * v;
            v = acc[nt][3]; s1 += v; q1v += v * v;
        }
        s0  += __shfl_xor_sync(0xffffffffu, s0, 1);  s0  += __shfl_xor_sync(0xffffffffu, s0, 2);
        q0v += __shfl_xor_sync(0xffffffffu, q0v, 1); q0v += __shfl_xor_sync(0xffffffffu, q0v, 2);
        s1  += __shfl_xor_sync(0xffffffffu, s1, 1);  s1  += __shfl_xor_sync(0xffffffffu, s1, 2);
        q1v += __shfl_xor_sync(0xffffffffu, q1v, 1); q1v += __shfl_xor_sync(0xffffffffu, q1v, 2);
        if (tig == 0) {
            redS[wc][rowBase+gid]   = s0; redQ[wc][rowBase+gid]   = q0v;
            redS[wc][rowBase+gid+8] = s1; redQ[wc][rowBase+gid+8] = q1v;
        }
    }
    __syncthreads();

#pragma unroll
    for (int hf = 0; hf < 2; hf++) {
        const int r = rowBase + gid + hf * 8;
        const float s = redS[0][r] + redS[1][r] + redS[2][r] + redS[3][r];
        const float q = redQ[0][r] + redQ[1][r] + redQ[2][r] + redQ[3][r];
        const float mu  = s * (1.f / 128.f);
        const float var = q * (1.f / 128.f) - mu * mu;
        const float inv = rsqrtf(var + EPS_);
        float* yr = Y + (size_t)(R0 + r) * E_ + C0 + colBase + tig * 2;
#pragma unroll
        for (int nt = 0; nt < 4; nt++) {
            float2 o;
            o.x = (acc[nt][hf*2+0] - mu) * inv * gv[nt*2+0] + g2[nt*2+0];
            o.y = (acc[nt][hf*2+1] - mu) * inv * gv[nt*2+1] + g2[nt*2+1];
            *(float2*)(yr + nt * 8) = o;
        }
    }
}

// =============================================================================
// Attention stage (unchanged from R9): one block per (b, h), 256 threads.
// =============================================================================
#define ATTN_DYN ((64*132 + 8*4*128) * 4)

__global__ void __launch_bounds__(256)
attn_kernel(const float* __restrict__ q,  const float* __restrict__ v1,
            const float* __restrict__ k,  const float* __restrict__ v2,
            const int*   __restrict__ mask,
            const float* __restrict__ Wb, const float* __restrict__ bb,
            const float* __restrict__ Ws, const float* __restrict__ bs,
            const float* __restrict__ Wc, const float* __restrict__ bc,
            float* __restrict__ out)
{
    extern __shared__ __align__(16) float dyn[];
    float* WbqT  = dyn;               // [64][132]
    float* kbufA = dyn + 64 * 132;    // [8][4][128]

    __shared__ float score[M_];
    __shared__ float wts[M_];
    __shared__ float maskf_s[M_];
    __shared__ float poolPart[8][MID_];
    __shared__ float pool[MID_];
    __shared__ float bbS[MID_], WsS[MID_];
    __shared__ float redA[8], redB[8], redC[8];
    __shared__ float v2part[2][DH];
    __shared__ float sMsInv, sMax, sSInv;

    const int tid  = threadIdx.x;
    const int lane = tid & 31;
    const int w    = tid >> 5;
    const int b    = blockIdx.x >> 3;
    const int h    = blockIdx.x & 7;

    const float* qp = q + (size_t)b * E_ + h * DH;

    for (int i = tid; i < DH * MID_; i += 256) {
        const int d = i >> 6, j = i & 63;
        WbqT[j * 132 + d] = qp[d] * Wb[i];
    }
    if (tid < MID_) { bbS[tid] = bb[tid]; WsS[tid] = Ws[tid]; }
    for (int i = tid; i < M_; i += 256) maskf_s[i] = (float)mask[(size_t)b * M_ + i];
    __syncthreads();

    const int j0 = lane, j1 = lane + 32;
    const float* kbase = k + (size_t)b * M_ * E_ + h * DH;
    float* kb = kbufA + w * 4 * 128;
    float pp0 = 0.f, pp1 = 0.f;

    for (int c = w; c < 49; c += 8) {
        const int mb = c * 4;
#pragma unroll
        for (int r = 0; r < 4; r++)
            ((float4*)(kb + r * 128))[lane] =
                ((const float4*)(kbase + (size_t)(mb + r) * E_))[lane];
        __syncwarp();

        float a[4][2];
#pragma unroll
        for (int r = 0; r < 4; r++) { a[r][0] = bbS[j0]; a[r][1] = bbS[j1]; }
#pragma unroll
        for (int d = 0; d < DH; d += 4) {
            const float4 w0 = *(const float4*)(WbqT + j0 * 132 + d);
            const float4 w1 = *(const float4*)(WbqT + j1 * 132 + d);
#pragma unroll
            for (int r = 0; r < 4; r++) {
                const float4 av = *(const float4*)(kb + r * 128 + d);
                a[r][0] += av.x * w0.x + av.y * w0.y + av.z * w0.z + av.w * w0.w;
                a[r][1] += av.x * w1.x + av.y * w1.y + av.z * w1.z + av.w * w1.w;
            }
        }
#pragma unroll
        for (int r = 0; r < 4; r++) {
            const float h0 = fmaxf(a[r][0], 0.f), h1 = fmaxf(a[r][1], 0.f);
            const float mf = maskf_s[mb + r];
            pp0 += h0 * mf;
            pp1 += h1 * mf;
            float p = h0 * WsS[j0] + h1 * WsS[j1];
#pragma unroll
            for (int o = 16; o > 0; o >>= 1) p += __shfl_xor_sync(0xffffffffu, p, o);
            if (lane == 0) score[mb + r] = p;
        }
        __syncwarp();
    }
    poolPart[w][j0] = pp0;
    poolPart[w][j1] = pp1;
    __syncthreads();

    if (tid < MID_) {
        float s = 0.f;
#pragma unroll
        for (int ww = 0; ww < 8; ww++) s += poolPart[ww][tid];
        pool[tid] = s;
    }
    {
        float ms = 0.f;
        for (int i = tid; i < M_; i += 256) ms += maskf_s[i];
#pragma unroll
        for (int o = 16; o > 0; o >>= 1) ms += __shfl_xor_sync(0xffffffffu, ms, o);
        if (lane == 0) redA[w] = ms;
    }
    __syncthreads();
    if (tid == 0) {
        float t = 0.f;
#pragma unroll
        for (int ww = 0; ww < 8; ww++) t += redA[ww];
        sMsInv = 1.f / t;
    }

    const float bs0 = bs[0];
    {
        float mx = -1e30f;
        for (int i = tid; i < M_; i += 256) {
            float s = (maskf_s[i] != 0.f) ? (score[i] + bs0) : -1e9f;
            score[i] = s;
            mx = fmaxf(mx, s);
        }
#pragma unroll
        for (int o = 16; o > 0; o >>= 1) mx = fmaxf(mx, __shfl_xor_sync(0xffffffffu, mx, o));
        if (lane == 0) redB[w] = mx;
    }
    __syncthreads();
    if (tid == 0) {
        float mx = -1e30f;
#pragma unroll
        for (int ww = 0; ww < 8; ww++) mx = fmaxf(mx, redB[ww]);
        sMax = mx;
    }
    __syncthreads();

    {
        const float mx = sMax;
        float se = 0.f;
        for (int i = tid; i < M_; i += 256) {
            float e = expf(score[i] - mx);
            wts[i] = e;
            se += e;
        }
#pragma unroll
        for (int o = 16; o > 0; o >>= 1) se += __shfl_xor_sync(0xffffffffu, se, o);
        if (lane == 0) redC[w] = se;
    }
    __syncthreads();
    if (tid == 0) {
        float t = 0.f;
#pragma unroll
        for (int ww = 0; ww < 8; ww++) t += redC[ww];
        sSInv = 1.f / t;
    }
    __syncthreads();

    {
        const int half = tid >> 7;
        const int d    = tid & 127;
        const float* v2base = v2 + (size_t)b * M_ * E_ + h * DH + d;
        float accv = 0.f;
        for (int m = half; m < M_; m += 2)
            accv += wts[m] * v2base[(size_t)m * E_];
        v2part[half][d] = accv;
    }
    __syncthreads();

    if (tid < DH) {
        const int d = tid;
        const float v2p = (v2part[0][d] + v2part[1][d]) * sSInv;
        const float msInv = sMsInv;
        float ac = bc[d];
#pragma unroll
        for (int j = 0; j < MID_; j++)
            ac += (pool[j] * msInv) * Wc[j * DH + d];
        const float sig = 1.f / (1.f + expf(-ac));
        out[(size_t)b * E_ + h * DH + d] = v1[(size_t)b * E_ + h * DH + d] * v2p * sig;
    }
}

// =============================================================================
// launch
// =============================================================================
extern "C" void kernel_launch(void* const* d_in, const int* in_sizes, int n_in,
                              void* d_out, int out_size)
{
    (void)in_sizes; (void)n_in; (void)out_size;
    const float* query  = (const float*)d_in[0];
    const float* key    = (const float*)d_in[1];
    const int*   mask   = (const int*  )d_in[2];
    const float* value1 = (const float*)d_in[3];
    const float* value2 = (const float*)d_in[4];
    const float* Wq = (const float*)d_in[5];
    const float* bq = (const float*)d_in[6];
    const float* gqw = (const float*)d_in[7];
    const float* gqb = (const float*)d_in[8];
    const float* Wk = (const float*)d_in[9];
    const float* bk = (const float*)d_in[10];
    const float* gkw = (const float*)d_in[11];
    const float* gkb = (const float*)d_in[12];
    const float* Wv1 = (const float*)d_in[13];
    const float* bv1 = (const float*)d_in[14];
    const float* gv1w = (const float*)d_in[15];
    const float* gv1b = (const float*)d_in[16];
    const float* Wv2 = (const float*)d_in[17];
    const float* bv2 = (const float*)d_in[18];
    const float* gv2w = (const float*)d_in[19];
    const float* gv2b = (const float*)d_in[20];
    const float* Wb = (const float*)d_in[21];
    const float* bb = (const float*)d_in[22];
    const float* Ws = (const float*)d_in[23];
    const float* bs = (const float*)d_in[24];
    const float* Wc = (const float*)d_in[25];
    const float* bc = (const float*)d_in[26];
    float* out = (float*)d_out;

    float *dq, *dv1, *dk, *dv2, *dWqr, *dWv1r, *dWkr, *dWv2r;
    cudaGetSymbolAddress((void**)&dq,    g_q);
    cudaGetSymbolAddress((void**)&dv1,   g_v1);
    cudaGetSymbolAddress((void**)&dk,    g_k);
    cudaGetSymbolAddress((void**)&dv2,   g_v2);
    cudaGetSymbolAddress((void**)&dWqr,  g_Wqr);
    cudaGetSymbolAddress((void**)&dWv1r, g_Wv1r);
    cudaGetSymbolAddress((void**)&dWkr,  g_Wkr);
    cudaGetSymbolAddress((void**)&dWv2r, g_Wv2r);

    cudaFuncSetAttribute(attn_kernel, cudaFuncAttributeMaxDynamicSharedMemorySize, ATTN_DYN);

    dim3 blk(256);
    // round all 4 weights to tf32-rna
    round_w4<<<dim3(1024, 4), blk>>>(Wq, Wv1, Wk, Wv2, dWqr, dWv1r, dWkr, dWv2r);
    // big projections first (better odds the ncu capture lands here)
    proj_big<<<dim3(8, NKV/128, 2), blk>>>(
        key,    dWkr,  bk,  gkw,  gkb,  dk,
        value2, dWv2r, bv2, gv2w, gv2b, dv2);
    // small projections (q + v1 in one launch)
    proj_small<<<dim3(8, 8, 2), blk>>>(
        query,  dWqr,  bq,  gqw,  gqb,  dq,
        value1, dWv1r, bv1, gv1w, gv1b, dv1);
    // attention stage
    attn_kernel<<<dim3(B_*H_), blk, ATTN_DYN>>>(dq, dv1, dk, dv2, mask,
                                                Wb, bb, Ws, bs, Wc, bc, out);
}

// round 12
// speedup vs baseline: 1.3716x; 1.0082x over previous
#include <cuda_runtime.h>
#include <math.h>
#include <stdint.h>

// Problem constants
#define B_   256
#define M_   196
#define E_   1024
#define H_   8
#define DH   128
#define MID_ 64
#define NKV  (B_*M_)
#define CELU_ALPHA 1.3f
#define EPS_ 1e-5f

// ---------------- scratch (device globals; no allocation allowed) -------------
__device__ float g_q  [B_*E_];
__device__ float g_v1 [B_*E_];
__device__ float g_k  [NKV*E_];
__device__ float g_v2 [NKV*E_];
__device__ float g_Wqr [E_*E_];
__device__ float g_Wv1r[E_*E_];
__device__ float g_Wkr [E_*E_];
__device__ float g_Wv2r[E_*E_];

// ---------------- helpers ----------------------------------------------------
static __device__ __forceinline__ float tf32r(float x) {
    unsigned u;
    asm("cvt.rna.tf32.f32 %0, %1;" : "=r"(u) : "f"(x));
    return __uint_as_float(u);
}
static __device__ __forceinline__ uint32_t smem_u32(const void* p) {
    uint32_t a;
    asm("{ .reg .u64 t; cvta.to.shared.u64 t, %1; cvt.u32.u64 %0, t; }" : "=r"(a) : "l"(p));
    return a;
}
#define CP_ASYNC16(dst, src) \
    asm volatile("cp.async.cg.shared.global [%0], [%1], 16;" :: "r"(dst), "l"(src))
#define CP_COMMIT() asm volatile("cp.async.commit_group;" ::: "memory")

#define MMA_TF32(acc, af, bf)                                                   \
    asm volatile(                                                               \
        "mma.sync.aligned.m16n8k8.row.col.f32.tf32.tf32.f32 "                   \
        "{%0,%1,%2,%3}, {%4,%5,%6,%7}, {%8,%9}, {%0,%1,%2,%3};\n"               \
        : "+f"((acc)[0]), "+f"((acc)[1]), "+f"((acc)[2]), "+f"((acc)[3])        \
        : "r"((af)[0]), "r"((af)[1]), "r"((af)[2]), "r"((af)[3]),               \
          "r"((bf)[0]), "r"((bf)[1]))

// =============================================================================
// tf32-rna round of all 4 weight matrices. grid (1024, 4), 256 thr.
// =============================================================================
__global__ void __launch_bounds__(256)
round_w4(const float* __restrict__ s0, const float* __restrict__ s1,
         const float* __restrict__ s2, const float* __restrict__ s3,
         float* __restrict__ d0, float* __restrict__ d1,
         float* __restrict__ d2, float* __restrict__ d3)
{
    const float* S; float* D;
    switch (blockIdx.y) {
        case 0:  S = s0; D = d0; break;
        case 1:  S = s1; D = d1; break;
        case 2:  S = s2; D = d2; break;
        default: S = s3; D = d3; break;
    }
    const int i = blockIdx.x * 256 + threadIdx.x;
    float4 v = ((const float4*)S)[i];
    ((float4*)D)[i] = make_float4(tf32r(v.x), tf32r(v.y), tf32r(v.z), tf32r(v.w));
}

// =============================================================================
// BIG fused projection (k + v2 via blockIdx.z):
//   Y = GroupNorm(celu(X @ W + b)) * gw + gb
// Block tile 128x128, 8 warps (2 row x 4 col), warp tile 64x32.
// 3-stage cp.async pipeline, ONE __syncthreads per chunk, 2 CTAs/SM.
// Dynamic smem 62.5KB. Grid: (8, nrows/128, 2).
// =============================================================================
#define PBA_STR 20
#define PBB_STR 136
#define PBA_ST  (128*PBA_STR)     // 2560 floats / stage
#define PBB_ST  (16*PBB_STR)      // 2176 floats / stage
#define PB_OPAR 0
#define PB_ORS  384
#define PB_ORQ  896
#define PB_OA   1408
#define PB_OB   (PB_OA + 3*PBA_ST)          // 9088
#define PB_DYN  ((PB_OB + 3*PBB_ST) * 4)    // 62464 bytes

__global__ void __launch_bounds__(256, 2)
proj_big(const float* __restrict__ X0, const float* __restrict__ W0,
         const float* __restrict__ b0, const float* __restrict__ g0,
         const float* __restrict__ q0, float* __restrict__ Y0,
         const float* __restrict__ X1, const float* __restrict__ W1,
         const float* __restrict__ b1, const float* __restrict__ g1,
         const float* __restrict__ q1, float* __restrict__ Y1)
{
    extern __shared__ __align__(16) float sm[];
    float* sPar = sm + PB_OPAR;
    float* redS = sm + PB_ORS;
    float* redQ = sm + PB_ORQ;

    const float *X, *W, *bias, *gw, *gb; float* Y;
    if (blockIdx.z == 0) { X = X0; W = W0; bias = b0; gw = g0; gb = q0; Y = Y0; }
    else                 { X = X1; W = W1; bias = b1; gw = g1; gb = q1; Y = Y1; }

    const int tid  = threadIdx.x;
    const int lane = tid & 31;
    const int warp = tid >> 5;
    const int gid  = lane >> 2;
    const int tig  = lane & 3;
    const int wr   = warp >> 2;          // 0..1
    const int wc   = warp & 3;           // 0..3
    const int rowBase = wr * 64;
    const int colBase = wc * 32;
    const int R0 = blockIdx.y * 128;
    const int C0 = blockIdx.x * 128;

    if (tid < 128) {
        sPar[tid]       = bias[C0 + tid];
        sPar[128 + tid] = gw  [C0 + tid];
        sPar[256 + tid] = gb  [C0 + tid];
    }

    const uint32_t aSm = smem_u32(sm + PB_OA);
    const uint32_t bSm = smem_u32(sm + PB_OB);
    const float* Xb = X + (size_t)R0 * E_;
    const float* Wb = W + C0;

    const int ar = tid >> 2, as_ = tid & 3;         // A: rows 0..63 (+64)
    const int br = tid >> 5, bc = tid & 31;         // B: rows 0..7  (+8)

#define PB_LOAD(k0, st) do {                                                   \
        const uint32_t aT = aSm + (st) * (PBA_ST * 4);                         \
        const uint32_t bT = bSm + (st) * (PBB_ST * 4);                         \
        CP_ASYNC16(aT + ar*80 + as_*16,        Xb + (size_t)ar * E_ + (k0) + as_*4);        \
        CP_ASYNC16(aT + (ar+64)*80 + as_*16,   Xb + (size_t)(ar+64) * E_ + (k0) + as_*4);   \
        CP_ASYNC16(bT + br*544 + bc*16,        Wb + (size_t)((k0) + br) * E_ + bc*4);       \
        CP_ASYNC16(bT + (br+8)*544 + bc*16,    Wb + (size_t)((k0) + br + 8) * E_ + bc*4);   \
    } while (0)

    float acc[4][4][4];
#pragma unroll
    for (int mt = 0; mt < 4; mt++)
#pragma unroll
        for (int nt = 0; nt < 4; nt++)
#pragma unroll
            for (int c = 0; c < 4; c++) acc[mt][nt][c] = 0.f;

    PB_LOAD(0, 0);  CP_COMMIT();
    PB_LOAD(16, 1); CP_COMMIT();

    int st = 0;                 // compute stage for chunk ch
    for (int ch = 0; ch < 64; ch++) {
        // chunk ch's group is 2 commits back -> leave only the newest pending
        asm volatile("cp.async.wait_group 1;" ::: "memory");
        __syncthreads();        // all threads' copies of chunk ch visible;
                                // all warps done reading stage we overwrite next
        if (ch + 2 < 64) {
            int ls = st + 2; if (ls >= 3) ls -= 3;
            PB_LOAD((ch + 2) * 16, ls);
        }
        CP_COMMIT();            // always commit (empty on tail) -> uniform counts

        const float* Ap = sm + PB_OA + st * PBA_ST;
        const float* Bp = sm + PB_OB + st * PBB_ST;
#pragma unroll
        for (int kk = 0; kk < 16; kk += 8) {
            unsigned af[4][4], bf[4][2];
#pragma unroll
            for (int mt = 0; mt < 4; mt++) {
                const int r = rowBase + mt * 16 + gid;
                af[mt][0] = __float_as_uint(Ap[ r      * PBA_STR + kk + tig    ]);
                af[mt][1] = __float_as_uint(Ap[(r + 8) * PBA_STR + kk + tig    ]);
                af[mt][2] = __float_as_uint(Ap[ r      * PBA_STR + kk + tig + 4]);
                af[mt][3] = __float_as_uint(Ap[(r + 8) * PBA_STR + kk + tig + 4]);
            }
#pragma unroll
            for (int nt = 0; nt < 4; nt++) {
                const int cb = colBase + nt * 8 + gid;
                bf[nt][0] = __float_as_uint(Bp[(kk + tig    ) * PBB_STR + cb]);
                bf[nt][1] = __float_as_uint(Bp[(kk + tig + 4) * PBB_STR + cb]);
            }
#pragma unroll
            for (int mt = 0; mt < 4; mt++)
#pragma unroll
                for (int nt = 0; nt < 4; nt++)
                    MMA_TF32(acc[mt][nt], af[mt], bf[nt]);
        }
        if (++st == 3) st = 0;
    }
#undef PB_LOAD
    __syncthreads();

    // ---------------- epilogue: bias + celu + GroupNorm ----------------
    float bv[8], gv[8], g2[8];
#pragma unroll
    for (int nt = 0; nt < 4; nt++)
#pragma unroll
        for (int cc = 0; cc < 2; cc++) {
            const int cl = colBase + nt * 8 + tig * 2 + cc;
            bv[nt*2+cc] = sPar[cl];
            gv[nt*2+cc] = sPar[128 + cl];
            g2[nt*2+cc] = sPar[256 + cl];
        }

#pragma unroll
    for (int mt = 0; mt < 4; mt++)
#pragma unroll
        for (int nt = 0; nt < 4; nt++)
#pragma unroll
            for (int c = 0; c < 4; c++) {
                float x = acc[mt][nt][c] + bv[nt*2 + (c & 1)];
                acc[mt][nt][c] = (x > 0.f) ? x : CELU_ALPHA * expm1f(x * (1.f / CELU_ALPHA));
            }

#pragma unroll
    for (int mt = 0; mt < 4; mt++) {
        float s0 = 0.f, q0v = 0.f, s1 = 0.f, q1v = 0.f;
#pragma unroll
        for (int nt = 0; nt < 4; nt++) {
            float v;
            v = acc[mt][nt][0]; s0 += v; q0v += v * v;
            v = acc[mt][nt][1]; s0 += v; q0v += v * v;
            v = acc[mt][nt][2]; s1 += v; q1v += v * v;
            v = acc[mt][nt][3]; s1 += v; q1v += v * v;
        }
        s0  += __shfl_xor_sync(0xffffffffu, s0, 1);  s0  += __shfl_xor_sync(0xffffffffu, s0, 2);
        q0v += __shfl_xor_sync(0xffffffffu, q0v, 1); q0v += __shfl_xor_sync(0xffffffffu, q0v, 2);
        s1  += __shfl_xor_sync(0xffffffffu, s1, 1);  s1  += __shfl_xor_sync(0xffffffffu, s1, 2);
        q1v += __shfl_xor_sync(0xffffffffu, q1v, 1); q1v += __shfl_xor_sync(0xffffffffu, q1v, 2);
        if (tig == 0) {
            const int r = rowBase + mt * 16 + gid;
            redS[wc * 128 + r]     = s0; redQ[wc * 128 + r]     = q0v;
            redS[wc * 128 + r + 8] = s1; redQ[wc * 128 + r + 8] = q1v;
        }
    }
    __syncthreads();

#pragma unroll
    for (int mt = 0; mt < 4; mt++)
#pragma unroll
        for (int hf = 0; hf < 2; hf++) {
            const int r = rowBase + mt * 16 + gid + hf * 8;
            const float s = redS[r] + redS[128 + r] + redS[256 + r] + redS[384 + r];
            const float q = redQ[r] + redQ[128 + r] + redQ[256 + r] + redQ[384 + r];
            const float mu  = s * (1.f / 128.f);
            const float var = q * (1.f / 128.f) - mu * mu;
            const float inv = rsqrtf(var + EPS_);
            float* yr = Y + (size_t)(R0 + r) * E_ + C0 + colBase + tig * 2;
#pragma unroll
            for (int nt = 0; nt < 4; nt++) {
                float2 o;
                o.x = (acc[mt][nt][hf*2+0] - mu) * inv * gv[nt*2+0] + g2[nt*2+0];
                o.y = (acc[mt][nt][hf*2+1] - mu) * inv * gv[nt*2+1] + g2[nt*2+1];
                *(float2*)(yr + nt * 8) = o;
            }
        }
}

// =============================================================================
// SMALL fused projection (q + v1 via blockIdx.z), 256 rows each. As R11.
// =============================================================================
#define PSA_ST 640
#define PSB_ST 2176
#define PS_ST  (PSA_ST + PSB_ST)

__global__ void __launch_bounds__(256)
proj_small(const float* __restrict__ X0, const float* __restrict__ W0,
           const float* __restrict__ b0, const float* __restrict__ g0,
           const float* __restrict__ q0, float* __restrict__ Y0,
           const float* __restrict__ X1, const float* __restrict__ W1,
           const float* __restrict__ b1, const float* __restrict__ g1,
           const float* __restrict__ q1, float* __restrict__ Y1)
{
    __shared__ __align__(16) float sm[3 * PS_ST];
    __shared__ float redS[4][32], redQ[4][32];

    const float *X, *W, *bias, *gw, *gb; float* Y;
    if (blockIdx.z == 0) { X = X0; W = W0; bias = b0; gw = g0; gb = q0; Y = Y0; }
    else                 { X = X1; W = W1; bias = b1; gw = g1; gb = q1; Y = Y1; }

    const int tid  = threadIdx.x;
    const int lane = tid & 31;
    const int warp = tid >> 5;
    const int gid  = lane >> 2;
    const int tig  = lane & 3;
    const int wr   = warp & 1;
    const int wc   = warp >> 1;
    const int rowBase = wr * 16;
    const int colBase = wc * 32;
    const int R0 = blockIdx.y * 32;
    const int C0 = blockIdx.x * 128;

    const uint32_t smB = smem_u32(sm);
    const float* Xb = X + (size_t)R0 * E_;
    const float* Wb = W + C0;

    const int ar = tid >> 2, as_ = tid & 3;
    const int br = tid >> 5, bc = tid & 31;

#define PS_LOAD(k0, st) do {                                                   \
        const uint32_t aT = smB + (st) * (PS_ST * 4);                          \
        const uint32_t bT = aT + PSA_ST * 4;                                   \
        if (tid < 128)                                                         \
            CP_ASYNC16(aT + ar*80 + as_*16, Xb + (size_t)ar * E_ + (k0) + as_*4); \
        CP_ASYNC16(bT + br*544 + bc*16,     Wb + (size_t)((k0) + br) * E_ + bc*4);       \
        CP_ASYNC16(bT + (br+8)*544 + bc*16, Wb + (size_t)((k0) + br + 8) * E_ + bc*4);   \
    } while (0)

    float acc[4][4];
#pragma unroll
    for (int nt = 0; nt < 4; nt++)
#pragma unroll
        for (int c = 0; c < 4; c++) acc[nt][c] = 0.f;

    PS_LOAD(0, 0);  CP_COMMIT();
    PS_LOAD(16, 1); CP_COMMIT();

    int st = 0;
    for (int ch = 0; ch < 64; ch++) {
        asm volatile("cp.async.wait_group 1;" ::: "memory");
        __syncthreads();
        if (ch + 2 < 64) {
            int ls = st + 2; if (ls >= 3) ls -= 3;
            PS_LOAD((ch + 2) * 16, ls);
        }
        CP_COMMIT();

        const float* Ap = sm + st * PS_ST;
        const float* Bp = Ap + PSA_ST;
#pragma unroll
        for (int kk = 0; kk < 16; kk += 8) {
            unsigned af[4], bf[4][2];
            const int r = rowBase + gid;
            af[0] = __float_as_uint(Ap[ r      * 20 + kk + tig    ]);
            af[1] = __float_as_uint(Ap[(r + 8) * 20 + kk + tig    ]);
            af[2] = __float_as_uint(Ap[ r      * 20 + kk + tig + 4]);
            af[3] = __float_as_uint(Ap[(r + 8) * 20 + kk + tig + 4]);
#pragma unroll
            for (int nt = 0; nt < 4; nt++) {
                const int cb = colBase + nt * 8 + gid;
                bf[nt][0] = __float_as_uint(Bp[(kk + tig    ) * 136 + cb]);
                bf[nt][1] = __float_as_uint(Bp[(kk + tig + 4) * 136 + cb]);
            }
#pragma unroll
            for (int nt = 0; nt < 4; nt++)
                MMA_TF32(acc[nt], af, bf[nt]);
        }
        if (++st == 3) st = 0;
    }
#undef PS_LOAD
    __syncthreads();

    // epilogue
    float bv[8], gv[8], g2[8];
#pragma unroll
    for (int nt = 0; nt < 4; nt++)
#pragma unroll
        for (int cc = 0; cc < 2; cc++) {
            const int cg = C0 + colBase + nt * 8 + tig * 2 + cc;
            bv[nt*2+cc] = bias[cg];
            gv[nt*2+cc] = gw[cg];
            g2[nt*2+cc] = gb[cg];
        }
#pragma unroll
    for (int nt = 0; nt < 4; nt++)
#pragma unroll
        for (int c = 0; c < 4; c++) {
            float x = acc[nt][c] + bv[nt*2 + (c & 1)];
            acc[nt][c] = (x > 0.f) ? x : CELU_ALPHA * expm1f(x * (1.f / CELU_ALPHA));
        }
    {
        float s0 = 0.f, q0v = 0.f, s1 = 0.f, q1v = 0.f;
#pragma unroll
        for (int nt = 0; nt < 4; nt++) {
            float v;
            v = acc[nt][0]; s0 += v; q0v += v * v;
            v = acc[nt][1]; s0 += v; q0v += v * v;
            v = acc[nt][2]; s1 += v; q1v += v * v;
            v = acc[nt][3]; s1 += v; q1v += v * v;
        }
        s0  += __shfl_xor_sync(0xffffffffu, s0, 1);  s0  += __shfl_xor_sync(0xffffffffu, s0, 2);
        q0v += __shfl_xor_sync(0xffffffffu, q0v, 1); q0v += __shfl_xor_sync(0xffffffffu, q0v, 2);
        s1  += __shfl_xor_sync(0xffffffffu, s1, 1);  s1  += __shfl_xor_sync(0xffffffffu, s1, 2);
        q1v += __shfl_xor_sync(0xffffffffu, q1v, 1); q1v += __shfl_xor_sync(0xffffffffu, q1v, 2);
        if (tig == 0) {
            redS[wc][rowBase+gid]   = s0; redQ[wc][rowBase+gid]   = q0v;
            redS[wc][rowBase+gid+8] = s1; redQ[wc][rowBase+gid+8] = q1v;
        }
    }
    __syncthreads();

#pragma unroll
    for (int hf = 0; hf < 2; hf++) {
        const int r = rowBase + gid + hf * 8;
        const float s = redS[0][r] + redS[1][r] + redS[2][r] + redS[3][r];
        const float q = redQ[0][r] + redQ[1][r] + redQ[2][r] + redQ[3][r];
        const float mu  = s * (1.f / 128.f);
        const float var = q * (1.f / 128.f) - mu * mu;
        const float inv = rsqrtf(var + EPS_);
        float* yr = Y + (size_t)(R0 + r) * E_ + C0 + colBase + tig * 2;
#pragma unroll
        for (int nt = 0; nt < 4; nt++) {
            float2 o;
            o.x = (acc[nt][hf*2+0] - mu) * inv * gv[nt*2+0] + g2[nt*2+0];
            o.y = (acc[nt][hf*2+1] - mu) * inv * gv[nt*2+1] + g2[nt*2+1];
            *(float2*)(yr + nt * 8) = o;
        }
    }
}

// =============================================================================
// Attention stage: one block per (b, h), 256 threads. Pass-1 uses 8-row
// m-chunks (WbqT registers reused over 8 rows -> half the crossbar traffic).
// =============================================================================
#define ATTN_DYN ((64*132 + 8*8*128) * 4)

__global__ void __launch_bounds__(256)
attn_kernel(const float* __restrict__ q,  const float* __restrict__ v1,
            const float* __restrict__ k,  const float* __restrict__ v2,
            const int*   __restrict__ mask,
            const float* __restrict__ Wb, const float* __restrict__ bb,
            const float* __restrict__ Ws, const float* __restrict__ bs,
            const float* __restrict__ Wc, const float* __restrict__ bc,
            float* __restrict__ out)
{
    extern __shared__ __align__(16) float dyn[];
    float* WbqT  = dyn;               // [64][132]
    float* kbufA = dyn + 64 * 132;    // [8][8][128]

    __shared__ float score[M_];
    __shared__ float wts[M_];
    __shared__ float maskf_s[M_];
    __shared__ float poolPart[8][MID_];
    __shared__ float pool[MID_];
    __shared__ float bbS[MID_], WsS[MID_];
    __shared__ float redA[8], redB[8], redC[8];
    __shared__ float v2part[2][DH];
    __shared__ float sMsInv, sMax, sSInv;

    const int tid  = threadIdx.x;
    const int lane = tid & 31;
    const int w    = tid >> 5;
    const int b    = blockIdx.x >> 3;
    const int h    = blockIdx.x & 7;

    const float* qp = q + (size_t)b * E_ + h * DH;

    for (int i = tid; i < DH * MID_; i += 256) {
        const int d = i >> 6, j = i & 63;
        WbqT[j * 132 + d] = qp[d] * Wb[i];
    }
    if (tid < MID_) { bbS[tid] = bb[tid]; WsS[tid] = Ws[tid]; }
    for (int i = tid; i < M_; i += 256) maskf_s[i] = (float)mask[(size_t)b * M_ + i];
    __syncthreads();

    // ---- pass 1: hidden GEMM in 8-row chunks (25 chunks, last guarded) ----
    const int j0 = lane, j1 = lane + 32;
    const float* kbase = k + (size_t)b * M_ * E_ + h * DH;
    float* kb = kbufA + w * 8 * 128;
    float pp0 = 0.f, pp1 = 0.f;

    for (int c = w; c < 25; c += 8) {
        const int mb = c * 8;
#pragma unroll
        for (int r = 0; r < 8; r++) {
            int mrow = mb + r; if (mrow > M_ - 1) mrow = M_ - 1;
            ((float4*)(kb + r * 128))[lane] =
                ((const float4*)(kbase + (size_t)mrow * E_))[lane];
        }
        __syncwarp();

        float a[8][2];
#pragma unroll
        for (int r = 0; r < 8; r++) { a[r][0] = bbS[j0]; a[r][1] = bbS[j1]; }
#pragma unroll
        for (int d = 0; d < DH; d += 4) {
            const float4 w0 = *(const float4*)(WbqT + j0 * 132 + d);
            const float4 w1 = *(const float4*)(WbqT + j1 * 132 + d);
#pragma unroll
            for (int r = 0; r < 8; r++) {
                const float4 av = *(const float4*)(kb + r * 128 + d);
                a[r][0] += av.x * w0.x + av.y * w0.y + av.z * w0.z + av.w * w0.w;
                a[r][1] += av.x * w1.x + av.y * w1.y + av.z * w1.z + av.w * w1.w;
            }
        }
#pragma unroll
        for (int r = 0; r < 8; r++) {
            const int m = mb + r;
            const float valid = (m < M_) ? 1.f : 0.f;
            const float h0 = fmaxf(a[r][0], 0.f), h1 = fmaxf(a[r][1], 0.f);
            const float mf = ((m < M_) ? maskf_s[m] : 0.f);
            pp0 += h0 * mf;
            pp1 += h1 * mf;
            float p = h0 * WsS[j0] + h1 * WsS[j1];
#pragma unroll
            for (int o = 16; o > 0; o >>= 1) p += __shfl_xor_sync(0xffffffffu, p, o);
            if (lane == 0 && valid != 0.f) score[m] = p;
        }
        __syncwarp();
    }
    poolPart[w][j0] = pp0;
    poolPart[w][j1] = pp1;
    __syncthreads();

    if (tid < MID_) {
        float s = 0.f;
#pragma unroll
        for (int ww = 0; ww < 8; ww++) s += poolPart[ww][tid];
        pool[tid] = s;
    }
    {
        float ms = 0.f;
        for (int i = tid; i < M_; i += 256) ms += maskf_s[i];
#pragma unroll
        for (int o = 16; o > 0; o >>= 1) ms += __shfl_xor_sync(0xffffffffu, ms, o);
        if (lane == 0) redA[w] = ms;
    }
    __syncthreads();
    if (tid == 0) {
        float t = 0.f;
#pragma unroll
        for (int ww = 0; ww < 8; ww++) t += redA[ww];
        sMsInv = 1.f / t;
    }

    const float bs0 = bs[0];
    {
        float mx = -1e30f;
        for (int i = tid; i < M_; i += 256) {
            float s = (maskf_s[i] != 0.f) ? (score[i] + bs0) : -1e9f;
            score[i] = s;
            mx = fmaxf(mx, s);
        }
#pragma unroll
        for (int o = 16; o > 0; o >>= 1) mx = fmaxf(mx, __shfl_xor_sync(0xffffffffu, mx, o));
        if (lane == 0) redB[w] = mx;
    }
    __syncthreads();
    if (tid == 0) {
        float mx = -1e30f;
#pragma unroll
        for (int ww = 0; ww < 8; ww++) mx = fmaxf(mx, redB[ww]);
        sMax = mx;
    }
    __syncthreads();

    {
        const float mx = sMax;
        float se = 0.f;
        for (int i = tid; i < M_; i += 256) {
            float e = expf(score[i] - mx);
            wts[i] = e;
            se += e;
        }
#pragma unroll
        for (int o = 16; o > 0; o >>= 1) se += __shfl_xor_sync(0xffffffffu, se, o);
        if (lane == 0) redC[w] = se;
    }
    __syncthreads();
    if (tid == 0) {
        float t = 0.f;
#pragma unroll
        for (int ww = 0; ww < 8; ww++) t += redC[ww];
        sSInv = 1.f / t;
    }
    __syncthreads();

    {
        const int half = tid >> 7;
        const int d    = tid & 127;
        const float* v2base = v2 + (size_t)b * M_ * E_ + h * DH + d;
        float accv = 0.f;
        for (int m = half; m < M_; m += 2)
            accv += wts[m] * v2base[(size_t)m * E_];
        v2part[half][d] = accv;
    }
    __syncthreads();

    if (tid < DH) {
        const int d = tid;
        const float v2p = (v2part[0][d] + v2part[1][d]) * sSInv;
        const float msInv = sMsInv;
        float ac = bc[d];
#pragma unroll
        for (int j = 0; j < MID_; j++)
            ac += (pool[j] * msInv) * Wc[j * DH + d];
        const float sig = 1.f / (1.f + expf(-ac));
        out[(size_t)b * E_ + h * DH + d] = v1[(size_t)b * E_ + h * DH + d] * v2p * sig;
    }
}

// =============================================================================
// launch
// =============================================================================
extern "C" void kernel_launch(void* const* d_in, const int* in_sizes, int n_in,
                              void* d_out, int out_size)
{
    (void)in_sizes; (void)n_in; (void)out_size;
    const float* query  = (const float*)d_in[0];
    const float* key    = (const float*)d_in[1];
    const int*   mask   = (const int*  )d_in[2];
    const float* value1 = (const float*)d_in[3];
    const float* value2 = (const float*)d_in[4];
    const float* Wq = (const float*)d_in[5];
    const float* bq = (const float*)d_in[6];
    const float* gqw = (const float*)d_in[7];
    const float* gqb = (const float*)d_in[8];
    const float* Wk = (const float*)d_in[9];
    const float* bk = (const float*)d_in[10];
    const float* gkw = (const float*)d_in[11];
    const float* gkb = (const float*)d_in[12];
    const float* Wv1 = (const float*)d_in[13];
    const float* bv1 = (const float*)d_in[14];
    const float* gv1w = (const float*)d_in[15];
    const float* gv1b = (const float*)d_in[16];
    const float* Wv2 = (const float*)d_in[17];
    const float* bv2 = (const float*)d_in[18];
    const float* gv2w = (const float*)d_in[19];
    const float* gv2b = (const float*)d_in[20];
    const float* Wb = (const float*)d_in[21];
    const float* bb = (const float*)d_in[22];
    const float* Ws = (const float*)d_in[23];
    const float* bs = (const float*)d_in[24];
    const float* Wc = (const float*)d_in[25];
    const float* bc = (const float*)d_in[26];
    float* out = (float*)d_out;

    float *dq, *dv1, *dk, *dv2, *dWqr, *dWv1r, *dWkr, *dWv2r;
    cudaGetSymbolAddress((void**)&dq,    g_q);
    cudaGetSymbolAddress((void**)&dv1,   g_v1);
    cudaGetSymbolAddress((void**)&dk,    g_k);
    cudaGetSymbolAddress((void**)&dv2,   g_v2);
    cudaGetSymbolAddress((void**)&dWqr,  g_Wqr);
    cudaGetSymbolAddress((void**)&dWv1r, g_Wv1r);
    cudaGetSymbolAddress((void**)&dWkr,  g_Wkr);
    cudaGetSymbolAddress((void**)&dWv2r, g_Wv2r);

    cudaFuncSetAttribute(proj_big, cudaFuncAttributeMaxDynamicSharedMemorySize, PB_DYN);
    cudaFuncSetAttribute(attn_kernel, cudaFuncAttributeMaxDynamicSharedMemorySize, ATTN_DYN);

    dim3 blk(256);
    round_w4<<<dim3(1024, 4), blk>>>(Wq, Wv1, Wk, Wv2, dWqr, dWv1r, dWkr, dWv2r);
    proj_big<<<dim3(8, NKV/128, 2), blk, PB_DYN>>>(
        key,    dWkr,  bk,  gkw,  gkb,  dk,
        value2, dWv2r, bv2, gv2w, gv2b, dv2);
    proj_small<<<dim3(8, 8, 2), blk>>>(
        query,  dWqr,  bq,  gqw,  gqb,  dq,
        value1, dWv1r, bv1, gv1w, gv1b, dv1);
    attn_kernel<<<dim3(B_*H_), blk, ATTN_DYN>>>(dq, dv1, dk, dv2, mask,
                                                Wb, bb, Ws, bs, Wc, bc, out);
}

// round 13
// speedup vs baseline: 1.4167x; 1.0329x over previous
#include <cuda_runtime.h>
#include <math.h>
#include <stdint.h>

// Problem constants
#define B_   256
#define M_   196
#define E_   1024
#define H_   8
#define DH   128
#define MID_ 64
#define NKV  (B_*M_)
#define CELU_ALPHA 1.3f
#define EPS_ 1e-5f

// ---------------- scratch (device globals; no allocation allowed) -------------
__device__ float g_q  [B_*E_];
__device__ float g_v1 [B_*E_];
__device__ float g_k  [NKV*E_];
__device__ float g_v2 [NKV*E_];
__device__ float g_Wqr [E_*E_];
__device__ float g_Wv1r[E_*E_];
__device__ float g_WkT [E_*E_];     // [n][k] transposed, tf32-rna
__device__ float g_Wv2T[E_*E_];     // [n][k] transposed, tf32-rna

// ---------------- helpers ----------------------------------------------------
static __device__ __forceinline__ float tf32r(float x) {
    unsigned u;
    asm("cvt.rna.tf32.f32 %0, %1;" : "=r"(u) : "f"(x));
    return __uint_as_float(u);
}
static __device__ __forceinline__ uint32_t smem_u32(const void* p) {
    uint32_t a;
    asm("{ .reg .u64 t; cvta.to.shared.u64 t, %1; cvt.u32.u64 %0, t; }" : "=r"(a) : "l"(p));
    return a;
}
#define CP_ASYNC16(dst, src) \
    asm volatile("cp.async.cg.shared.global [%0], [%1], 16;" :: "r"(dst), "l"(src))
#define CP_COMMIT() asm volatile("cp.async.commit_group;" ::: "memory")

#define MMA_TF32(acc, af, bf)                                                   \
    asm volatile(                                                               \
        "mma.sync.aligned.m16n8k8.row.col.f32.tf32.tf32.f32 "                   \
        "{%0,%1,%2,%3}, {%4,%5,%6,%7}, {%8,%9}, {%0,%1,%2,%3};\n"               \
        : "+f"((acc)[0]), "+f"((acc)[1]), "+f"((acc)[2]), "+f"((acc)[3])        \
        : "r"((af)[0]), "r"((af)[1]), "r"((af)[2]), "r"((af)[3]),               \
          "r"((bf)[0]), "r"((bf)[1]))

#define LDSM_X4(r0, r1, r2, r3, addr)                                           \
    asm volatile("ldmatrix.sync.aligned.m8n8.x4.shared.b16 {%0,%1,%2,%3}, [%4];"\
        : "=r"(r0), "=r"(r1), "=r"(r2), "=r"(r3) : "r"(addr))

// =============================================================================
// tf32-rna round (elementwise) of Wq, Wv1. grid (1024, 2), 256 thr.
// =============================================================================
__global__ void __launch_bounds__(256)
round_w2(const float* __restrict__ s0, const float* __restrict__ s1,
         float* __restrict__ d0, float* __restrict__ d1)
{
    const float* S = blockIdx.y ? s1 : s0;
    float*       D = blockIdx.y ? d1 : d0;
    const int i = blockIdx.x * 256 + threadIdx.x;
    float4 v = ((const float4*)S)[i];
    ((float4*)D)[i] = make_float4(tf32r(v.x), tf32r(v.y), tf32r(v.z), tf32r(v.w));
}

// =============================================================================
// transpose + tf32-rna round: Wt[n][k] = tf32(W[k][n]). grid (32,32,2).
// =============================================================================
__global__ void __launch_bounds__(256)
transpose_tf32(const float* __restrict__ W0, float* __restrict__ Wt0,
               const float* __restrict__ W1, float* __restrict__ Wt1)
{
    __shared__ float t[32][33];
    const float* W  = blockIdx.z ? W1  : W0;
    float*       Wt = blockIdx.z ? Wt1 : Wt0;
    const int bx = blockIdx.x * 32, by = blockIdx.y * 32;
    const int tx = threadIdx.x & 31, ty = threadIdx.x >> 5;  // 32x8
#pragma unroll
    for (int i = 0; i < 32; i += 8)
        t[ty + i][tx] = tf32r(W[(size_t)(by + ty + i) * E_ + bx + tx]);
    __syncthreads();
#pragma unroll
    for (int i = 0; i < 32; i += 8)
        Wt[(size_t)(bx + ty + i) * E_ + by + tx] = t[tx][ty + i];
}

// =============================================================================
// BIG fused projection (k + v2 via blockIdx.z):
//   Y = GroupNorm(celu(X @ W + b)) * gw + gb
// Block tile 128x128, 8 warps (2 row x 4 col), warp tile 64x32.
// A smem [row][k] stride 20; B smem [n][k] stride 20 (from W^T).
// Fragments via ldmatrix.x4 (12 per warp-chunk vs 48 scalar LDS).
// 3-stage cp.async pipeline, one barrier/chunk, 2 CTAs/SM.
// =============================================================================
#define PBA_STR 20
#define PBA_ST  (128*PBA_STR)     // 2560 floats / stage (A)
#define PBB_ST  (128*PBA_STR)     // 2560 floats / stage (B, [n][k] stride 20)
#define PB_OPAR 0
#define PB_ORS  384
#define PB_ORQ  896
#define PB_OA   1408
#define PB_OB   (PB_OA + 3*PBA_ST)          // 9088
#define PB_DYN  ((PB_OB + 3*PBB_ST) * 4)    // 67072 bytes

__global__ void __launch_bounds__(256, 2)
proj_big(const float* __restrict__ X0, const float* __restrict__ WT0,
         const float* __restrict__ b0, const float* __restrict__ g0,
         const float* __restrict__ q0, float* __restrict__ Y0,
         const float* __restrict__ X1, const float* __restrict__ WT1,
         const float* __restrict__ b1, const float* __restrict__ g1,
         const float* __restrict__ q1, float* __restrict__ Y1)
{
    extern __shared__ __align__(16) float sm[];
    float* sPar = sm + PB_OPAR;
    float* redS = sm + PB_ORS;
    float* redQ = sm + PB_ORQ;

    const float *X, *WT, *bias, *gw, *gb; float* Y;
    if (blockIdx.z == 0) { X = X0; WT = WT0; bias = b0; gw = g0; gb = q0; Y = Y0; }
    else                 { X = X1; WT = WT1; bias = b1; gw = g1; gb = q1; Y = Y1; }

    const int tid  = threadIdx.x;
    const int lane = tid & 31;
    const int warp = tid >> 5;
    const int gid  = lane >> 2;
    const int tig  = lane & 3;
    const int wr   = warp >> 2;          // 0..1
    const int wc   = warp & 3;           // 0..3
    const int rowBase = wr * 64;
    const int colBase = wc * 32;
    const int R0 = blockIdx.y * 128;
    const int C0 = blockIdx.x * 128;

    if (tid < 128) {
        sPar[tid]       = bias[C0 + tid];
        sPar[128 + tid] = gw  [C0 + tid];
        sPar[256 + tid] = gb  [C0 + tid];
    }

    const uint32_t aSm = smem_u32(sm + PB_OA);
    const uint32_t bSm = smem_u32(sm + PB_OB);
    const float* Xb  = X  + (size_t)R0 * E_;
    const float* WTb = WT + (size_t)C0 * E_;

    // cp.async lane mapping (both tiles are 128 rows x 16 k, stride 20 floats)
    const int ar = tid >> 2, as_ = tid & 3;

    // ldmatrix per-lane offsets (bytes, within a stage)
    //   A tiles: t = l>>3; row += (t&1)*8; kbyte += (t>>1)*16
    const uint32_t aLaneOff =
        (uint32_t)(rowBase + (lane & 7) + ((lane >> 3) & 1) * 8) * 80u
        + (uint32_t)((lane >> 4) & 1) * 16u;
    //   B tiles: t = l>>3; n += (t>>1)*8; kbyte += (t&1)*16
    const uint32_t bLaneOff =
        (uint32_t)(colBase + (lane & 7) + ((lane >> 4) & 1) * 8) * 80u
        + (uint32_t)((lane >> 3) & 1) * 16u;

#define PB_LOAD(k0, st) do {                                                   \
        const uint32_t aT = aSm + (st) * (PBA_ST * 4);                         \
        const uint32_t bT = bSm + (st) * (PBB_ST * 4);                         \
        CP_ASYNC16(aT + ar*80 + as_*16,        Xb  + (size_t)ar * E_ + (k0) + as_*4);       \
        CP_ASYNC16(aT + (ar+64)*80 + as_*16,   Xb  + (size_t)(ar+64) * E_ + (k0) + as_*4);  \
        CP_ASYNC16(bT + ar*80 + as_*16,        WTb + (size_t)ar * E_ + (k0) + as_*4);       \
        CP_ASYNC16(bT + (ar+64)*80 + as_*16,   WTb + (size_t)(ar+64) * E_ + (k0) + as_*4);  \
    } while (0)

    float acc[4][4][4];
#pragma unroll
    for (int mt = 0; mt < 4; mt++)
#pragma unroll
        for (int nt = 0; nt < 4; nt++)
#pragma unroll
            for (int c = 0; c < 4; c++) acc[mt][nt][c] = 0.f;

    PB_LOAD(0, 0);  CP_COMMIT();
    PB_LOAD(16, 1); CP_COMMIT();

    int st = 0;
    for (int ch = 0; ch < 64; ch++) {
        asm volatile("cp.async.wait_group 1;" ::: "memory");
        __syncthreads();
        if (ch + 2 < 64) {
            int ls = st + 2; if (ls >= 3) ls -= 3;
            PB_LOAD((ch + 2) * 16, ls);
        }
        CP_COMMIT();

        const uint32_t aT = aSm + st * (PBA_ST * 4);
        const uint32_t bT = bSm + st * (PBB_ST * 4);
#pragma unroll
        for (int kk = 0; kk < 2; kk++) {
            const uint32_t kOff = kk * 32u;
            unsigned af[4][4], bf[4][2];
#pragma unroll
            for (int mt = 0; mt < 4; mt++)
                LDSM_X4(af[mt][0], af[mt][1], af[mt][2], af[mt][3],
                        aT + aLaneOff + mt * 1280u + kOff);
#pragma unroll
            for (int p = 0; p < 2; p++)
                LDSM_X4(bf[2*p][0], bf[2*p][1], bf[2*p+1][0], bf[2*p+1][1],
                        bT + bLaneOff + p * 1280u + kOff);
#pragma unroll
            for (int mt = 0; mt < 4; mt++)
#pragma unroll
                for (int nt = 0; nt < 4; nt++)
                    MMA_TF32(acc[mt][nt], af[mt], bf[nt]);
        }
        if (++st == 3) st = 0;
    }
#undef PB_LOAD
    __syncthreads();

    // ---------------- epilogue: bias + celu + GroupNorm ----------------
    float bv[8], gv[8], g2[8];
#pragma unroll
    for (int nt = 0; nt < 4; nt++)
#pragma unroll
        for (int cc = 0; cc < 2; cc++) {
            const int cl = colBase + nt * 8 + tig * 2 + cc;
            bv[nt*2+cc] = sPar[cl];
            gv[nt*2+cc] = sPar[128 + cl];
            g2[nt*2+cc] = sPar[256 + cl];
        }

#pragma unroll
    for (int mt = 0; mt < 4; mt++)
#pragma unroll
        for (int nt = 0; nt < 4; nt++)
#pragma unroll
            for (int c = 0; c < 4; c++) {
                float x = acc[mt][nt][c] + bv[nt*2 + (c & 1)];
                acc[mt][nt][c] = (x > 0.f) ? x : CELU_ALPHA * expm1f(x * (1.f / CELU_ALPHA));
            }

#pragma unroll
    for (int mt = 0; mt < 4; mt++) {
        float s0 = 0.f, q0v = 0.f, s1 = 0.f, q1v = 0.f;
#pragma unroll
        for (int nt = 0; nt < 4; nt++) {
            float v;
            v = acc[mt][nt][0]; s0 += v; q0v += v * v;
            v = acc[mt][nt][1]; s0 += v; q0v += v * v;
            v = acc[mt][nt][2]; s1 += v; q1v += v * v;
            v = acc[mt][nt][3]; s1 += v; q1v += v * v;
        }
        s0  += __shfl_xor_sync(0xffffffffu, s0, 1);  s0  += __shfl_xor_sync(0xffffffffu, s0, 2);
        q0v += __shfl_xor_sync(0xffffffffu, q0v, 1); q0v += __shfl_xor_sync(0xffffffffu, q0v, 2);
        s1  += __shfl_xor_sync(0xffffffffu, s1, 1);  s1  += __shfl_xor_sync(0xffffffffu, s1, 2);
        q1v += __shfl_xor_sync(0xffffffffu, q1v, 1); q1v += __shfl_xor_sync(0xffffffffu, q1v, 2);
        if (tig == 0) {
            const int r = rowBase + mt * 16 + gid;
            redS[wc * 128 + r]     = s0; redQ[wc * 128 + r]     = q0v;
            redS[wc * 128 + r + 8] = s1; redQ[wc * 128 + r + 8] = q1v;
        }
    }
    __syncthreads();

#pragma unroll
    for (int mt = 0; mt < 4; mt++)
#pragma unroll
        for (int hf = 0; hf < 2; hf++) {
            const int r = rowBase + mt * 16 + gid + hf * 8;
            const float s = redS[r] + redS[128 + r] + redS[256 + r] + redS[384 + r];
            const float q = redQ[r] + redQ[128 + r] + redQ[256 + r] + redQ[384 + r];
            const float mu  = s * (1.f / 128.f);
            const float var = q * (1.f / 128.f) - mu * mu;
            const float inv = rsqrtf(var + EPS_);
            float* yr = Y + (size_t)(R0 + r) * E_ + C0 + colBase + tig * 2;
#pragma unroll
            for (int nt = 0; nt < 4; nt++) {
                float2 o;
                o.x = (acc[mt][nt][hf*2+0] - mu) * inv * gv[nt*2+0] + g2[nt*2+0];
                o.y = (acc[mt][nt][hf*2+1] - mu) * inv * gv[nt*2+1] + g2[nt*2+1];
                *(float2*)(yr + nt * 8) = o;
            }
        }
}

// =============================================================================
// SMALL fused projection (q + v1 via blockIdx.z), 256 rows each. As R12.
// =============================================================================
#define PSA_ST 640
#define PSB_ST 2176
#define PS_ST  (PSA_ST + PSB_ST)

__global__ void __launch_bounds__(256)
proj_small(const float* __restrict__ X0, const float* __restrict__ W0,
           const float* __restrict__ b0, const float* __restrict__ g0,
           const float* __restrict__ q0, float* __restrict__ Y0,
           const float* __restrict__ X1, const float* __restrict__ W1,
           const float* __restrict__ b1, const float* __restrict__ g1,
           const float* __restrict__ q1, float* __restrict__ Y1)
{
    __shared__ __align__(16) float sm[3 * PS_ST];
    __shared__ float redS[4][32], redQ[4][32];

    const float *X, *W, *bias, *gw, *gb; float* Y;
    if (blockIdx.z == 0) { X = X0; W = W0; bias = b0; gw = g0; gb = q0; Y = Y0; }
    else                 { X = X1; W = W1; bias = b1; gw = g1; gb = q1; Y = Y1; }

    const int tid  = threadIdx.x;
    const int lane = tid & 31;
    const int warp = tid >> 5;
    const int gid  = lane >> 2;
    const int tig  = lane & 3;
    const int wr   = warp & 1;
    const int wc   = warp >> 1;
    const int rowBase = wr * 16;
    const int colBase = wc * 32;
    const int R0 = blockIdx.y * 32;
    const int C0 = blockIdx.x * 128;

    const uint32_t smB = smem_u32(sm);
    const float* Xb = X + (size_t)R0 * E_;
    const float* Wb = W + C0;

    const int ar = tid >> 2, as_ = tid & 3;
    const int br = tid >> 5, bc = tid & 31;

#define PS_LOAD(k0, st) do {                                                   \
        const uint32_t aT = smB + (st) * (PS_ST * 4);                          \
        const uint32_t bT = aT + PSA_ST * 4;                                   \
        if (tid < 128)                                                         \
            CP_ASYNC16(aT + ar*80 + as_*16, Xb + (size_t)ar * E_ + (k0) + as_*4); \
        CP_ASYNC16(bT + br*544 + bc*16,     Wb + (size_t)((k0) + br) * E_ + bc*4);       \
        CP_ASYNC16(bT + (br+8)*544 + bc*16, Wb + (size_t)((k0) + br + 8) * E_ + bc*4);   \
    } while (0)

    float acc[4][4];
#pragma unroll
    for (int nt = 0; nt < 4; nt++)
#pragma unroll
        for (int c = 0; c < 4; c++) acc[nt][c] = 0.f;

    PS_LOAD(0, 0);  CP_COMMIT();
    PS_LOAD(16, 1); CP_COMMIT();

    int st = 0;
    for (int ch = 0; ch < 64; ch++) {
        asm volatile("cp.async.wait_group 1;" ::: "memory");
        __syncthreads();
        if (ch + 2 < 64) {
            int ls = st + 2; if (ls >= 3) ls -= 3;
            PS_LOAD((ch + 2) * 16, ls);
        }
        CP_COMMIT();

        const float* Ap = sm + st * PS_ST;
        const float* Bp = Ap + PSA_ST;
#pragma unroll
        for (int kk = 0; kk < 16; kk += 8) {
            unsigned af[4], bf[4][2];
            const int r = rowBase + gid;
            af[0] = __float_as_uint(Ap[ r      * 20 + kk + tig    ]);
            af[1] = __float_as_uint(Ap[(r + 8) * 20 + kk + tig    ]);
            af[2] = __float_as_uint(Ap[ r      * 20 + kk + tig + 4]);
            af[3] = __float_as_uint(Ap[(r + 8) * 20 + kk + tig + 4]);
#pragma unroll
            for (int nt = 0; nt < 4; nt++) {
                const int cb = colBase + nt * 8 + gid;
                bf[nt][0] = __float_as_uint(Bp[(kk + tig    ) * 136 + cb]);
                bf[nt][1] = __float_as_uint(Bp[(kk + tig + 4) * 136 + cb]);
            }
#pragma unroll
            for (int nt = 0; nt < 4; nt++)
                MMA_TF32(acc[nt], af, bf[nt]);
        }
        if (++st == 3) st = 0;
    }
#undef PS_LOAD
    __syncthreads();

    // epilogue
    float bv[8], gv[8], g2[8];
#pragma unroll
    for (int nt = 0; nt < 4; nt++)
#pragma unroll
        for (int cc = 0; cc < 2; cc++) {
            const int cg = C0 + colBase + nt * 8 + tig * 2 + cc;
            bv[nt*2+cc] = bias[cg];
            gv[nt*2+cc] = gw[cg];
            g2[nt*2+cc] = gb[cg];
        }
#pragma unroll
    for (int nt = 0; nt < 4; nt++)
#pragma unroll
        for (int c = 0; c < 4; c++) {
            float x = acc[nt][c] + bv[nt*2 + (c & 1)];
            acc[nt][c] = (x > 0.f) ? x : CELU_ALPHA * expm1f(x * (1.f / CELU_ALPHA));
        }
    {
        float s0 = 0.f, q0v = 0.f, s1 = 0.f, q1v = 0.f;
#pragma unroll
        for (int nt = 0; nt < 4; nt++) {
            float v;
            v = acc[nt][0]; s0 += v; q0v += v * v;
            v = acc[nt][1]; s0 += v; q0v += v * v;
            v = acc[nt][2]; s1 += v; q1v += v * v;
            v = acc[nt][3]; s1 += v; q1v += v * v;
        }
        s0  += __shfl_xor_sync(0xffffffffu, s0, 1);  s0  += __shfl_xor_sync(0xffffffffu, s0, 2);
        q0v += __shfl_xor_sync(0xffffffffu, q0v, 1); q0v += __shfl_xor_sync(0xffffffffu, q0v, 2);
        s1  += __shfl_xor_sync(0xffffffffu, s1, 1);  s1  += __shfl_xor_sync(0xffffffffu, s1, 2);
        q1v += __shfl_xor_sync(0xffffffffu, q1v, 1); q1v += __shfl_xor_sync(0xffffffffu, q1v, 2);
        if (tig == 0) {
            redS[wc][rowBase+gid]   = s0; redQ[wc][rowBase+gid]   = q0v;
            redS[wc][rowBase+gid+8] = s1; redQ[wc][rowBase+gid+8] = q1v;
        }
    }
    __syncthreads();

#pragma unroll
    for (int hf = 0; hf < 2; hf++) {
        const int r = rowBase + gid + hf * 8;
        const float s = redS[0][r] + redS[1][r] + redS[2][r] + redS[3][r];
        const float q = redQ[0][r] + redQ[1][r] + redQ[2][r] + redQ[3][r];
        const float mu  = s * (1.f / 128.f);
        const float var = q * (1.f / 128.f) - mu * mu;
        const float inv = rsqrtf(var + EPS_);
        float* yr = Y + (size_t)(R0 + r) * E_ + C0 + colBase + tig * 2;
#pragma unroll
        for (int nt = 0; nt < 4; nt++) {
            float2 o;
            o.x = (acc[nt][hf*2+0] - mu) * inv * gv[nt*2+0] + g2[nt*2+0];
            o.y = (acc[nt][hf*2+1] - mu) * inv * gv[nt*2+1] + g2[nt*2+1];
            *(float2*)(yr + nt * 8) = o;
        }
    }
}

// =============================================================================
// Attention stage (unchanged from R12): 8-row m-chunks, one block per (b,h).
// =============================================================================
#define ATTN_DYN ((64*132 + 8*8*128) * 4)

__global__ void __launch_bounds__(256)
attn_kernel(const float* __restrict__ q,  const float* __restrict__ v1,
            const float* __restrict__ k,  const float* __restrict__ v2,
            const int*   __restrict__ mask,
            const float* __restrict__ Wb, const float* __restrict__ bb,
            const float* __restrict__ Ws, const float* __restrict__ bs,
            const float* __restrict__ Wc, const float* __restrict__ bc,
            float* __restrict__ out)
{
    extern __shared__ __align__(16) float dyn[];
    float* WbqT  = dyn;               // [64][132]
    float* kbufA = dyn + 64 * 132;    // [8][8][128]

    __shared__ float score[M_];
    __shared__ float wts[M_];
    __shared__ float maskf_s[M_];
    __shared__ float poolPart[8][MID_];
    __shared__ float pool[MID_];
    __shared__ float bbS[MID_], WsS[MID_];
    __shared__ float redA[8], redB[8], redC[8];
    __shared__ float v2part[2][DH];
    __shared__ float sMsInv, sMax, sSInv;

    const int tid  = threadIdx.x;
    const int lane = tid & 31;
    const int w    = tid >> 5;
    const int b    = blockIdx.x >> 3;
    const int h    = blockIdx.x & 7;

    const float* qp = q + (size_t)b * E_ + h * DH;

    for (int i = tid; i < DH * MID_; i += 256) {
        const int d = i >> 6, j = i & 63;
        WbqT[j * 132 + d] = qp[d] * Wb[i];
    }
    if (tid < MID_) { bbS[tid] = bb[tid]; WsS[tid] = Ws[tid]; }
    for (int i = tid; i < M_; i += 256) maskf_s[i] = (float)mask[(size_t)b * M_ + i];
    __syncthreads();

    const int j0 = lane, j1 = lane + 32;
    const float* kbase = k + (size_t)b * M_ * E_ + h * DH;
    float* kb = kbufA + w * 8 * 128;
    float pp0 = 0.f, pp1 = 0.f;

    for (int c = w; c < 25; c += 8) {
        const int mb = c * 8;
#pragma unroll
        for (int r = 0; r < 8; r++) {
            int mrow = mb + r; if (mrow > M_ - 1) mrow = M_ - 1;
            ((float4*)(kb + r * 128))[lane] =
                ((const float4*)(kbase + (size_t)mrow * E_))[lane];
        }
        __syncwarp();

        float a[8][2];
#pragma unroll
        for (int r = 0; r < 8; r++) { a[r][0] = bbS[j0]; a[r][1] = bbS[j1]; }
#pragma unroll
        for (int d = 0; d < DH; d += 4) {
            const float4 w0 = *(const float4*)(WbqT + j0 * 132 + d);
            const float4 w1 = *(const float4*)(WbqT + j1 * 132 + d);
#pragma unroll
            for (int r = 0; r < 8; r++) {
                const float4 av = *(const float4*)(kb + r * 128 + d);
                a[r][0] += av.x * w0.x + av.y * w0.y + av.z * w0.z + av.w * w0.w;
                a[r][1] += av.x * w1.x + av.y * w1.y + av.z * w1.z + av.w * w1.w;
            }
        }
#pragma unroll
        for (int r = 0; r < 8; r++) {
            const int m = mb + r;
            const float valid = (m < M_) ? 1.f : 0.f;
            const float h0 = fmaxf(a[r][0], 0.f), h1 = fmaxf(a[r][1], 0.f);
            const float mf = ((m < M_) ? maskf_s[m] : 0.f);
            pp0 += h0 * mf;
            pp1 += h1 * mf;
            float p = h0 * WsS[j0] + h1 * WsS[j1];
#pragma unroll
            for (int o = 16; o > 0; o >>= 1) p += __shfl_xor_sync(0xffffffffu, p, o);
            if (lane == 0 && valid != 0.f) score[m] = p;
        }
        __syncwarp();
    }
    poolPart[w][j0] = pp0;
    poolPart[w][j1] = pp1;
    __syncthreads();

    if (tid < MID_) {
        float s = 0.f;
#pragma unroll
        for (int ww = 0; ww < 8; ww++) s += poolPart[ww][tid];
        pool[tid] = s;
    }
    {
        float ms = 0.f;
        for (int i = tid; i < M_; i += 256) ms += maskf_s[i];
#pragma unroll
        for (int o = 16; o > 0; o >>= 1) ms += __shfl_xor_sync(0xffffffffu, ms, o);
        if (lane == 0) redA[w] = ms;
    }
    __syncthreads();
    if (tid == 0) {
        float t = 0.f;
#pragma unroll
        for (int ww = 0; ww < 8; ww++) t += redA[ww];
        sMsInv = 1.f / t;
    }

    const float bs0 = bs[0];
    {
        float mx = -1e30f;
        for (int i = tid; i < M_; i += 256) {
            float s = (maskf_s[i] != 0.f) ? (score[i] + bs0) : -1e9f;
            score[i] = s;
            mx = fmaxf(mx, s);
        }
#pragma unroll
        for (int o = 16; o > 0; o >>= 1) mx = fmaxf(mx, __shfl_xor_sync(0xffffffffu, mx, o));
        if (lane == 0) redB[w] = mx;
    }
    __syncthreads();
    if (tid == 0) {
        float mx = -1e30f;
#pragma unroll
        for (int ww = 0; ww < 8; ww++) mx = fmaxf(mx, redB[ww]);
        sMax = mx;
    }
    __syncthreads();

    {
        const float mx = sMax;
        float se = 0.f;
        for (int i = tid; i < M_; i += 256) {
            float e = expf(score[i] - mx);
            wts[i] = e;
            se += e;
        }
#pragma unroll
        for (int o = 16; o > 0; o >>= 1) se += __shfl_xor_sync(0xffffffffu, se, o);
        if (lane == 0) redC[w] = se;
    }
    __syncthreads();
    if (tid == 0) {
        float t = 0.f;
#pragma unroll
        for (int ww = 0; ww < 8; ww++) t += redC[ww];
        sSInv = 1.f / t;
    }
    __syncthreads();

    {
        const int half = tid >> 7;
        const int d    = tid & 127;
        const float* v2base = v2 + (size_t)b * M_ * E_ + h * DH + d;
        float accv = 0.f;
        for (int m = half; m < M_; m += 2)
            accv += wts[m] * v2base[(size_t)m * E_];
        v2part[half][d] = accv;
    }
    __syncthreads();

    if (tid < DH) {
        const int d = tid;
        const float v2p = (v2part[0][d] + v2part[1][d]) * sSInv;
        const float msInv = sMsInv;
        float ac = bc[d];
#pragma unroll
        for (int j = 0; j < MID_; j++)
            ac += (pool[j] * msInv) * Wc[j * DH + d];
        const float sig = 1.f / (1.f + expf(-ac));
        out[(size_t)b * E_ + h * DH + d] = v1[(size_t)b * E_ + h * DH + d] * v2p * sig;
    }
}

// =============================================================================
// launch
// =============================================================================
extern "C" void kernel_launch(void* const* d_in, const int* in_sizes, int n_in,
                              void* d_out, int out_size)
{
    (void)in_sizes; (void)n_in; (void)out_size;
    const float* query  = (const float*)d_in[0];
    const float* key    = (const float*)d_in[1];
    const int*   mask   = (const int*  )d_in[2];
    const float* value1 = (const float*)d_in[3];
    const float* value2 = (const float*)d_in[4];
    const float* Wq = (const float*)d_in[5];
    const float* bq = (const float*)d_in[6];
    const float* gqw = (const float*)d_in[7];
    const float* gqb = (const float*)d_in[8];
    const float* Wk = (const float*)d_in[9];
    const float* bk = (const float*)d_in[10];
    const float* gkw = (const float*)d_in[11];
    const float* gkb = (const float*)d_in[12];
    const float* Wv1 = (const float*)d_in[13];
    const float* bv1 = (const float*)d_in[14];
    const float* gv1w = (const float*)d_in[15];
    const float* gv1b = (const float*)d_in[16];
    const float* Wv2 = (const float*)d_in[17];
    const float* bv2 = (const float*)d_in[18];
    const float* gv2w = (const float*)d_in[19];
    const float* gv2b = (const float*)d_in[20];
    const float* Wb = (const float*)d_in[21];
    const float* bb = (const float*)d_in[22];
    const float* Ws = (const float*)d_in[23];
    const float* bs = (const float*)d_in[24];
    const float* Wc = (const float*)d_in[25];
    const float* bc = (const float*)d_in[26];
    float* out = (float*)d_out;

    float *dq, *dv1, *dk, *dv2, *dWqr, *dWv1r, *dWkT, *dWv2T;
    cudaGetSymbolAddress((void**)&dq,    g_q);
    cudaGetSymbolAddress((void**)&dv1,   g_v1);
    cudaGetSymbolAddress((void**)&dk,    g_k);
    cudaGetSymbolAddress((void**)&dv2,   g_v2);
    cudaGetSymbolAddress((void**)&dWqr,  g_Wqr);
    cudaGetSymbolAddress((void**)&dWv1r, g_Wv1r);
    cudaGetSymbolAddress((void**)&dWkT,  g_WkT);
    cudaGetSymbolAddress((void**)&dWv2T, g_Wv2T);

    cudaFuncSetAttribute(proj_big, cudaFuncAttributeMaxDynamicSharedMemorySize, PB_DYN);
    cudaFuncSetAttribute(attn_kernel, cudaFuncAttributeMaxDynamicSharedMemorySize, ATTN_DYN);

    dim3 blk(256);
    // weight prep: elementwise round for small projs; transpose+round for big
    round_w2<<<dim3(1024, 2), blk>>>(Wq, Wv1, dWqr, dWv1r);
    transpose_tf32<<<dim3(32, 32, 2), blk>>>(Wk, dWkT, Wv2, dWv2T);
    // big projections (ldmatrix + [n][k] B layout)
    proj_big<<<dim3(8, NKV/128, 2), blk, PB_DYN>>>(
        key,    dWkT,  bk,  gkw,  gkb,  dk,
        value2, dWv2T, bv2, gv2w, gv2b, dv2);
    // small projections
    proj_small<<<dim3(8, 8, 2), blk>>>(
        query,  dWqr,  bq,  gqw,  gqb,  dq,
        value1, dWv1r, bv1, gv1w, gv1b, dv1);
    // attention stage
    attn_kernel<<<dim3(B_*H_), blk, ATTN_DYN>>>(dq, dv1, dk, dv2, mask,
                                                Wb, bb, Ws, bs, Wc, bc, out);
}